// round 12
// baseline (speedup 1.0000x reference)
#include <cuda_runtime.h>
#include <cuda_fp16.h>
#include <math.h>

#define DIMW 3072
#define NH 24
#define HD 128
#define TXT_N 512
#define REF_N 512
#define STOT_N 2560
#define SHID_N 2048
#define WELTS (DIMW * DIMW)

// ---- scratch (device globals; no allocations allowed) ----
__device__ float g_q[STOT_N * DIMW];
__device__ float g_k[STOT_N * DIMW];
__device__ float g_v[STOT_N * DIMW];
// packed fp16 planes (2 fp16 per u32)
__device__ unsigned g_af[STOT_N * DIMW / 2];
__device__ unsigned g_wf[8ull * WELTS / 2];

// ---- helpers ----
__device__ __forceinline__ unsigned pk16(float a, float b) {   // a -> low half
    __half2 h = __floats2half2_rn(a, b);
    return *(unsigned*)&h;
}
__device__ __forceinline__ void mmaf(float* c, const unsigned* a, unsigned b0, unsigned b1) {
    asm volatile("mma.sync.aligned.m16n8k16.row.col.f32.f16.f16.f32 "
        "{%0,%1,%2,%3}, {%4,%5,%6,%7}, {%8,%9}, {%0,%1,%2,%3};\n"
        : "+f"(c[0]), "+f"(c[1]), "+f"(c[2]), "+f"(c[3])
        : "r"(a[0]), "r"(a[1]), "r"(a[2]), "r"(a[3]), "r"(b0), "r"(b1));
}
__device__ __forceinline__ void cpa16(unsigned saddr, const void* g) {
    asm volatile("cp.async.ca.shared.global [%0], [%1], 16;\n" :: "r"(saddr), "l"(g));
}
#define LDSM4(r0,r1,r2,r3,addr) \
    asm volatile("ldmatrix.sync.aligned.m8n8.x4.shared.b16 {%0,%1,%2,%3},[%4];" \
        : "=r"(r0),"=r"(r1),"=r"(r2),"=r"(r3) : "r"(addr))
#define LDSM4T(r0,r1,r2,r3,addr) \
    asm volatile("ldmatrix.sync.aligned.m8n8.x4.trans.shared.b16 {%0,%1,%2,%3},[%4];" \
        : "=r"(r0),"=r"(r1),"=r"(r2),"=r"(r3) : "r"(addr))

// ============================================================================
// fp32 -> packed fp16 plane
// ============================================================================
__global__ void __launch_bounds__(256) convf(const float* __restrict__ s,
        unsigned* __restrict__ d, int n4)
{
    int i = blockIdx.x * 256 + threadIdx.x;
    if (i >= n4) return;
    float4 x = ((const float4*)s)[i];
    uint2 H;
    H.x = pk16(x.x, x.y);
    H.y = pk16(x.z, x.w);
    ((uint2*)d)[i] = H;
}

// batched weight convert: 8 weights, z selects
struct WSrc { const float* p[8]; };
__global__ void __launch_bounds__(256) wconv_all(WSrc ws, unsigned* __restrict__ d)
{
    const float* __restrict__ W = ws.p[blockIdx.z];
    size_t base = (size_t)blockIdx.z * (WELTS / 2);
    int i = blockIdx.x * 256 + threadIdx.x + blockIdx.y * (256 * 96);
    float4 x = ((const float4*)W)[i];
    uint2 H;
    H.x = pk16(x.x, x.y);
    H.y = pk16(x.z, x.w);
    ((uint2*)(d + base))[i] = H;
}

// ============================================================================
// fp16 GEMM: C[M,3072] = A @ W + bias, single MMA term.
// BM=128, BN=128, BK=64 per stage, 3-stage cp.async, 256 threads = 8 warps
// (4m x 2n), warp tile 32x64, m16n8k16, ldmatrix fragments. 2 CTAs/SM.
// 48 iterations, one __syncthreads per 64 MMAs/warp (was 96 / 32).
// Row-range dual weights (txt rows < 512 use set A). blockIdx.z selects op.
// ============================================================================
struct DualW {
    const unsigned* B_a; const float* bias_a; float* C_a;
    const unsigned* B_b; const float* bias_b; float* C_b;
};
struct GemmArgs {
    const unsigned* A;
    DualW w[3];
};

#define BM 128
#define BN 128
#define SA_T (BM * 36)            // 4608 u32/stage, A rows 144B (128 data + 16 pad)
#define SB_T (64 * 68)            // 4352 u32/stage, B rows 272B (256 data + 16 pad)
#define STG4 ((SA_T + SB_T) * 4)  // 35840 B
#define GEMM_SMEM (3 * STG4)      // 107520 B

__global__ void __launch_bounds__(256, 2) gemm_f16(GemmArgs ga)
{
    extern __shared__ unsigned smg[];

    const DualW& w = ga.w[blockIdx.z];
    const int mBase = blockIdx.y * BM;
    const int nBase = blockIdx.x * BN;
    const bool low = (mBase < TXT_N);
    const unsigned* __restrict__ B = low ? w.B_a : w.B_b;
    const float* __restrict__ bias = low ? w.bias_a : w.bias_b;
    float* __restrict__ C = low ? (w.C_a + (size_t)mBase * DIMW)
                                : (w.C_b + (size_t)(mBase - TXT_N) * DIMW);
    const unsigned* __restrict__ A = ga.A;

    const int tid  = threadIdx.x;
    const int lane = tid & 31;
    const int warp = tid >> 5;
    const int wm = warp >> 1;     // 0..3
    const int wn = warp & 1;      // 0..1

    const unsigned smBase = (unsigned)__cvta_generic_to_shared(smg);
    const int quad = lane >> 3;
    const unsigned offA = (unsigned)((wm * 32 + (lane & 7) + (quad & 1) * 8) * 144 + (quad >> 1) * 16);
    const unsigned offB = (unsigned)(((lane & 7) + (quad & 1) * 8) * 272 + (wn * 64 + (quad >> 1) * 8) * 2);

    // per-thread cp.async source/dest (hoisted; advance by constants per stage)
    const int aRow = tid >> 1, aSeg = tid & 1;           // 128 rows x 2 thr; 4 segs each
    const int bRow = tid >> 2, bSeg = tid & 3;           // 64 rows x 4 thr; 4 segs each

    auto load_stage = [&](int kb, int buf) {
        unsigned base = smBase + buf * STG4;
        // A: 128 rows x 8 segs of 16B = 1024 cpa; each thread 4 (strided seg)
        #pragma unroll
        for (int i = 0; i < 4; i++) {
            int seg = aSeg * 4 + i;
            size_t g = (size_t)(mBase + aRow) * (DIMW / 2) + kb * 32 + seg * 4;
            cpa16(base + aRow * 144 + seg * 16, A + g);
        }
        // B: 64 rows x 16 segs of 16B = 1024 cpa; each thread 4
        #pragma unroll
        for (int i = 0; i < 4; i++) {
            int seg = bSeg * 4 + i;
            size_t g = (size_t)(kb * 64 + bRow) * (DIMW / 2) + (nBase >> 1) + seg * 4;
            cpa16(base + SA_T * 4 + bRow * 272 + seg * 16, B + g);
        }
        asm volatile("cp.async.commit_group;\n");
    };

    float acc[2][8][4];
    #pragma unroll
    for (int i = 0; i < 2; i++)
        #pragma unroll
        for (int j = 0; j < 8; j++)
            #pragma unroll
            for (int p = 0; p < 4; p++) acc[i][j][p] = 0.f;

    const int NK = DIMW / 64;   // 48
    load_stage(0, 0);
    load_stage(1, 1);

    int buf = 0;
    for (int kb = 0; kb < NK; kb++) {
        if (kb + 2 < NK) {
            asm volatile("cp.async.wait_group 1;\n");
        } else {
            asm volatile("cp.async.wait_group 0;\n");
        }
        __syncthreads();
        if (kb + 2 < NK) load_stage(kb + 2, (kb + 2) % 3);

        const unsigned stb = smBase + buf * STG4;
        const unsigned aP = stb + offA;
        const unsigned bP = stb + SA_T * 4 + offB;

        #pragma unroll
        for (int k16 = 0; k16 < 4; k16++) {
            unsigned a[2][4];
            #pragma unroll
            for (int mt = 0; mt < 2; mt++)
                LDSM4(a[mt][0], a[mt][1], a[mt][2], a[mt][3], aP + mt * (16 * 144) + k16 * 32);
            #pragma unroll
            for (int p = 0; p < 4; p++) {
                unsigned bh[4];
                LDSM4T(bh[0], bh[1], bh[2], bh[3], bP + k16 * (16 * 272) + p * 32);
                #pragma unroll
                for (int h = 0; h < 2; h++)
                    #pragma unroll
                    for (int mt = 0; mt < 2; mt++)
                        mmaf(acc[mt][p * 2 + h], a[mt], bh[2 * h], bh[2 * h + 1]);
            }
        }
        buf = (buf + 1) % 3;
    }

    #pragma unroll
    for (int mt = 0; mt < 2; mt++) {
        int r = wm * 32 + mt * 16 + (lane >> 2);
        #pragma unroll
        for (int nt = 0; nt < 8; nt++) {
            int cg = nBase + wn * 64 + nt * 8 + (lane & 3) * 2;
            float b0 = bias[cg], b1 = bias[cg + 1];
            float2 v0 = make_float2(acc[mt][nt][0] + b0, acc[mt][nt][1] + b1);
            float2 v1 = make_float2(acc[mt][nt][2] + b0, acc[mt][nt][3] + b1);
            *(float2*)&C[(size_t)r * DIMW + cg] = v0;
            *(float2*)&C[(size_t)(r + 8) * DIMW + cg] = v1;
        }
    }
}

// ============================================================================
// Fused per-head RMSNorm + interleaved RoPE, in place on q and k (fp32).
// ============================================================================
__global__ void __launch_bounds__(128) norm_rope(float* __restrict__ q, float* __restrict__ k,
        const float* __restrict__ nq, const float* __restrict__ nk,
        const float* __restrict__ naq, const float* __restrict__ nak,
        const float* __restrict__ rc, const float* __restrict__ rs)
{
    const int gw   = blockIdx.x * 4 + (threadIdx.x >> 5);
    const int lane = threadIdx.x & 31;
    const int t = gw / NH, h = gw % NH;
    const size_t base = (size_t)t * DIMW + h * HD + lane * 4;
    const float* wq = (t < TXT_N) ? naq : nq;
    const float* wk = (t < TXT_N) ? nak : nk;
    const float4 c4 = *(const float4*)(rc + (size_t)t * HD + lane * 4);
    const float4 s4 = *(const float4*)(rs + (size_t)t * HD + lane * 4);

    #pragma unroll
    for (int which = 0; which < 2; which++) {
        float* buf = which ? k : q;
        const float* wv = which ? wk : wq;
        float4 x = *(float4*)(buf + base);
        float ss = x.x * x.x + x.y * x.y + x.z * x.z + x.w * x.w;
        ss += __shfl_xor_sync(0xffffffffu, ss, 16);
        ss += __shfl_xor_sync(0xffffffffu, ss, 8);
        ss += __shfl_xor_sync(0xffffffffu, ss, 4);
        ss += __shfl_xor_sync(0xffffffffu, ss, 2);
        ss += __shfl_xor_sync(0xffffffffu, ss, 1);
        float r = rsqrtf(ss * (1.0f / HD) + 1e-6f);
        float4 w4 = *(const float4*)(wv + lane * 4);
        x.x *= r * w4.x; x.y *= r * w4.y; x.z *= r * w4.z; x.w *= r * w4.w;
        float4 y;
        y.x = x.x * c4.x - x.y * s4.x;
        y.y = x.y * c4.y + x.x * s4.y;
        y.z = x.z * c4.z - x.w * s4.z;
        y.w = x.w * c4.w + x.z * s4.w;
        *(float4*)(buf + base) = y;
    }
}

// ============================================================================
// Flash attention, all-fp16 MMA (single term). QK: m16n8k16, PV: m16n8k16 with
// V fragments via ldmatrix.trans. Epilogue writes packed fp16 plane (fused
// convert for the out projection).
// ============================================================================
#define QS 68
#define KS 68
#define VS 68
#define PS 36
#define V_OFF (64 * QS + 64 * KS)            // u32 offset of V
#define P_OFF (V_OFF + 64 * VS)
#define FLASH_SMEM ((P_OFF + 64 * PS) * 4)   // 61440 B

__global__ void __launch_bounds__(128) flash(const float* __restrict__ q,
        const float* __restrict__ k, const float* __restrict__ v,
        unsigned* __restrict__ of)
{
    extern __shared__ unsigned sm[];
    unsigned* Qs = sm;
    unsigned* Ks = Qs + 64 * QS;
    unsigned* Vs = sm + V_OFF;
    unsigned* Ps = sm + P_OFF;
    const unsigned smBase = (unsigned)__cvta_generic_to_shared(sm);

    const int tid = threadIdx.x, lane = tid & 31, w = tid >> 5;
    const int qt = blockIdx.x, h = blockIdx.y;
    const int qb = qt * 64;
    const bool isref = (qb >= TXT_N) && (qb < TXT_N + REF_N);
    const int kv0 = isref ? TXT_N : 0;
    const int nkt = isref ? (REF_N / 64) : (STOT_N / 64);

    // ldmatrix.trans per-lane offset into V (k-rows x n-cols, 272B rows)
    const int quad = lane >> 3;
    const unsigned offV = (unsigned)(((lane & 7) + (quad & 1) * 8) * (VS * 4) + (quad >> 1) * 16);
    const unsigned vB = smBase + V_OFF * 4 + offV;

    // load Q tile 64x128 -> packed fp16
    #pragma unroll
    for (int i = 0; i < 16; i++) {
        int f = tid + i * 128;
        int row = f >> 5, d4 = f & 31;
        float4 x = *(const float4*)(q + (size_t)(qb + row) * DIMW + h * HD + d4 * 4);
        Qs[row * QS + d4 * 2]     = pk16(x.x, x.y);
        Qs[row * QS + d4 * 2 + 1] = pk16(x.z, x.w);
    }

    float O[16][4];
    #pragma unroll
    for (int i = 0; i < 16; i++)
        #pragma unroll
        for (int j = 0; j < 4; j++) O[i][j] = 0.f;
    float m0 = -1e30f, m1 = -1e30f, l0 = 0.f, l1 = 0.f;
    const int r0 = w * 16 + (lane >> 2);

    for (int it = 0; it < nkt; it++) {
        __syncthreads();
        const int kt0 = kv0 + it * 64;
        #pragma unroll
        for (int i = 0; i < 16; i++) {
            int f = tid + i * 128;
            int row = f >> 5, d4 = f & 31;
            float4 x = *(const float4*)(k + (size_t)(kt0 + row) * DIMW + h * HD + d4 * 4);
            Ks[row * KS + d4 * 2]     = pk16(x.x, x.y);
            Ks[row * KS + d4 * 2 + 1] = pk16(x.z, x.w);
            float4 y = *(const float4*)(v + (size_t)(kt0 + row) * DIMW + h * HD + d4 * 4);
            Vs[row * VS + d4 * 2]     = pk16(y.x, y.y);
            Vs[row * VS + d4 * 2 + 1] = pk16(y.z, y.w);
        }
        __syncthreads();

        // S = Q @ K^T  (fp16 m16n8k16, 8 k-steps x 8 n-tiles)
        float s[8][4];
        #pragma unroll
        for (int i = 0; i < 8; i++)
            #pragma unroll
            for (int j = 0; j < 4; j++) s[i][j] = 0.f;
        #pragma unroll
        for (int ks = 0; ks < 8; ks++) {
            const int kp = ks * 8 + (lane & 3);
            unsigned a[4];
            a[0] = Qs[r0 * QS + kp];       a[1] = Qs[(r0 + 8) * QS + kp];
            a[2] = Qs[r0 * QS + kp + 4];   a[3] = Qs[(r0 + 8) * QS + kp + 4];
            #pragma unroll
            for (int nt = 0; nt < 8; nt++) {
                int bn = nt * 8 + (lane >> 2);
                mmaf(s[nt], a, Ks[bn * KS + kp], Ks[bn * KS + kp + 4]);
            }
        }
        // online softmax
        const float sc = 0.08838834764831845f;
        float rm0 = -1e30f, rm1 = -1e30f;
        #pragma unroll
        for (int nt = 0; nt < 8; nt++) {
            s[nt][0] *= sc; s[nt][1] *= sc; s[nt][2] *= sc; s[nt][3] *= sc;
            rm0 = fmaxf(rm0, fmaxf(s[nt][0], s[nt][1]));
            rm1 = fmaxf(rm1, fmaxf(s[nt][2], s[nt][3]));
        }
        rm0 = fmaxf(rm0, __shfl_xor_sync(0xffffffffu, rm0, 1));
        rm0 = fmaxf(rm0, __shfl_xor_sync(0xffffffffu, rm0, 2));
        rm1 = fmaxf(rm1, __shfl_xor_sync(0xffffffffu, rm1, 1));
        rm1 = fmaxf(rm1, __shfl_xor_sync(0xffffffffu, rm1, 2));
        float mn0 = fmaxf(m0, rm0), mn1 = fmaxf(m1, rm1);
        float al0 = __expf(m0 - mn0), al1 = __expf(m1 - mn1);
        float rs0 = 0.f, rs1 = 0.f;
        #pragma unroll
        for (int nt = 0; nt < 8; nt++) {
            s[nt][0] = __expf(s[nt][0] - mn0); s[nt][1] = __expf(s[nt][1] - mn0);
            s[nt][2] = __expf(s[nt][2] - mn1); s[nt][3] = __expf(s[nt][3] - mn1);
            rs0 += s[nt][0] + s[nt][1];
            rs1 += s[nt][2] + s[nt][3];
        }
        rs0 += __shfl_xor_sync(0xffffffffu, rs0, 1);
        rs0 += __shfl_xor_sync(0xffffffffu, rs0, 2);
        rs1 += __shfl_xor_sync(0xffffffffu, rs1, 1);
        rs1 += __shfl_xor_sync(0xffffffffu, rs1, 2);
        l0 = l0 * al0 + rs0; l1 = l1 * al1 + rs1;
        m0 = mn0; m1 = mn1;
        #pragma unroll
        for (int nt = 0; nt < 16; nt++) {
            O[nt][0] *= al0; O[nt][1] *= al0; O[nt][2] *= al1; O[nt][3] *= al1;
        }
        // P -> smem packed fp16
        #pragma unroll
        for (int nt = 0; nt < 8; nt++) {
            int pc = nt * 4 + (lane & 3);
            Ps[r0 * PS + pc]       = pk16(s[nt][0], s[nt][1]);
            Ps[(r0 + 8) * PS + pc] = pk16(s[nt][2], s[nt][3]);
        }
        __syncwarp();
        // O += P @ V  (fp16 m16n8k16, 4 k-steps x 8 n16-groups, ldmatrix.trans V)
        #pragma unroll
        for (int ks = 0; ks < 4; ks++) {
            const int kp = ks * 8 + (lane & 3);
            unsigned a[4];
            a[0] = Ps[r0 * PS + kp];       a[1] = Ps[(r0 + 8) * PS + kp];
            a[2] = Ps[r0 * PS + kp + 4];   a[3] = Ps[(r0 + 8) * PS + kp + 4];
            #pragma unroll
            for (int p = 0; p < 8; p++) {
                unsigned bh[4];
                LDSM4T(bh[0], bh[1], bh[2], bh[3], vB + ks * (16 * VS * 4) + p * 32);
                mmaf(O[p * 2],     a, bh[0], bh[1]);
                mmaf(O[p * 2 + 1], a, bh[2], bh[3]);
            }
        }
    }
    // epilogue: normalize + write packed fp16 plane
    const float i0 = 1.f / l0, i1 = 1.f / l1;
    const int tok0 = qb + r0;
    #pragma unroll
    for (int nt = 0; nt < 16; nt++) {
        int cp = h * (HD / 2) + nt * 4 + (lane & 3);
        of[(size_t)tok0 * (DIMW / 2) + cp]       = pk16(O[nt][0] * i0, O[nt][1] * i0);
        of[(size_t)(tok0 + 8) * (DIMW / 2) + cp] = pk16(O[nt][2] * i1, O[nt][3] * i1);
    }
}

extern "C" void kernel_launch(void* const* d_in, const int* in_sizes, int n_in,
                              void* d_out, int out_size) {
    const float* hs  = (const float*)d_in[0];
    const float* enc = (const float*)d_in[1];
    const float* rc  = (const float*)d_in[2];
    const float* rs  = (const float*)d_in[3];
    const float* wq  = (const float*)d_in[4];
    const float* bq  = (const float*)d_in[5];
    const float* wk  = (const float*)d_in[6];
    const float* bk  = (const float*)d_in[7];
    const float* wv  = (const float*)d_in[8];
    const float* bv  = (const float*)d_in[9];
    const float* waq = (const float*)d_in[10];
    const float* baq = (const float*)d_in[11];
    const float* wak = (const float*)d_in[12];
    const float* bak = (const float*)d_in[13];
    const float* wav = (const float*)d_in[14];
    const float* bav = (const float*)d_in[15];
    const float* nq  = (const float*)d_in[16];
    const float* nk  = (const float*)d_in[17];
    const float* naq = (const float*)d_in[18];
    const float* nak = (const float*)d_in[19];
    const float* wo  = (const float*)d_in[20];
    const float* bo  = (const float*)d_in[21];
    const float* wao = (const float*)d_in[22];
    const float* bao = (const float*)d_in[23];
    float* out = (float*)d_out;

    float *qp, *kp, *vp;
    unsigned *afp, *wfp;
    cudaGetSymbolAddress((void**)&qp, g_q);
    cudaGetSymbolAddress((void**)&kp, g_k);
    cudaGetSymbolAddress((void**)&vp, g_v);
    cudaGetSymbolAddress((void**)&afp, g_af);
    cudaGetSymbolAddress((void**)&wfp, g_wf);

    cudaFuncSetAttribute(flash, cudaFuncAttributeMaxDynamicSharedMemorySize, FLASH_SMEM);
    cudaFuncSetAttribute(gemm_f16, cudaFuncAttributeMaxDynamicSharedMemorySize, GEMM_SMEM);

    const size_t WP = (size_t)WELTS / 2;
    const size_t AROW = DIMW / 2;

    // 0) weights (one batched launch; order wq wk wv waq wak wav wo wao)
    {
        WSrc ws;
        ws.p[0] = wq; ws.p[1] = wk; ws.p[2] = wv; ws.p[3] = waq;
        ws.p[4] = wak; ws.p[5] = wav; ws.p[6] = wo; ws.p[7] = wao;
        wconv_all<<<dim3(96, 96, 8), 256>>>(ws, wfp);
    }
    // 1-2) activations: rows [0,512)=enc, [512,2560)=hs
    convf<<<TXT_N * DIMW / 4 / 256, 256>>>(enc, afp, TXT_N * DIMW / 4);
    convf<<<SHID_N * DIMW / 4 / 256, 256>>>(hs, afp + TXT_N * AROW, SHID_N * DIMW / 4);

    // 3) fused QKV projection: grid (24, 20, 3) = 1440 CTAs, 2 CTAs/SM
    {
        GemmArgs ga;
        ga.A = afp;
        ga.w[0].B_a = wfp + 3ull * WP; ga.w[0].bias_a = baq; ga.w[0].C_a = qp;
        ga.w[0].B_b = wfp;            ga.w[0].bias_b = bq;
        ga.w[0].C_b = qp + (size_t)TXT_N * DIMW;
        ga.w[1].B_a = wfp + 4ull * WP; ga.w[1].bias_a = bak; ga.w[1].C_a = kp;
        ga.w[1].B_b = wfp + 1ull * WP; ga.w[1].bias_b = bk;
        ga.w[1].C_b = kp + (size_t)TXT_N * DIMW;
        ga.w[2].B_a = wfp + 5ull * WP; ga.w[2].bias_a = bav; ga.w[2].C_a = vp;
        ga.w[2].B_b = wfp + 2ull * WP; ga.w[2].bias_b = bv;
        ga.w[2].C_b = vp + (size_t)TXT_N * DIMW;
        gemm_f16<<<dim3(24, 20, 3), 256, GEMM_SMEM>>>(ga);
    }

    // 4) norm + rope
    norm_rope<<<STOT_N * NH / 4, 128>>>(qp, kp, nq, nk, naq, nak, rc, rs);

    // 5) flash (writes packed fp16 plane directly)
    flash<<<dim3(STOT_N / 64, NH), 128, FLASH_SMEM>>>(qp, kp, vp, afp);

    // 6) fused out projection: grid (24, 20)
    {
        GemmArgs ga;
        ga.A = afp;
        ga.w[0].B_a = wfp + 7ull * WP; ga.w[0].bias_a = bao;
        ga.w[0].C_a = out + (size_t)SHID_N * DIMW;
        ga.w[0].B_b = wfp + 6ull * WP; ga.w[0].bias_b = bo;
        ga.w[0].C_b = out;
        ga.w[1] = ga.w[0]; ga.w[2] = ga.w[0];
        gemm_f16<<<dim3(24, 20, 1), 256, GEMM_SMEM>>>(ga);
    }
}

// round 13
// speedup vs baseline: 1.3700x; 1.3700x over previous
#include <cuda_runtime.h>
#include <cuda_fp16.h>
#include <math.h>

#define DIMW 3072
#define NH 24
#define HD 128
#define TXT_N 512
#define REF_N 512
#define STOT_N 2560
#define SHID_N 2048
#define WELTS (DIMW * DIMW)

// ---- scratch (device globals; no allocations allowed) ----
// q/k/v now packed fp16 (2 per u32)
__device__ unsigned g_q[STOT_N * DIMW / 2];
__device__ unsigned g_k[STOT_N * DIMW / 2];
__device__ unsigned g_v[STOT_N * DIMW / 2];
// packed fp16 planes (2 fp16 per u32)
__device__ unsigned g_af[STOT_N * DIMW / 2];
__device__ unsigned g_wf[8ull * WELTS / 2];

// ---- helpers ----
__device__ __forceinline__ unsigned pk16(float a, float b) {   // a -> low half
    __half2 h = __floats2half2_rn(a, b);
    return *(unsigned*)&h;
}
__device__ __forceinline__ float2 up16(unsigned u) {
    return __half22float2(*(__half2*)&u);
}
__device__ __forceinline__ void mmaf(float* c, const unsigned* a, unsigned b0, unsigned b1) {
    asm volatile("mma.sync.aligned.m16n8k16.row.col.f32.f16.f16.f32 "
        "{%0,%1,%2,%3}, {%4,%5,%6,%7}, {%8,%9}, {%0,%1,%2,%3};\n"
        : "+f"(c[0]), "+f"(c[1]), "+f"(c[2]), "+f"(c[3])
        : "r"(a[0]), "r"(a[1]), "r"(a[2]), "r"(a[3]), "r"(b0), "r"(b1));
}
__device__ __forceinline__ void cpa16(unsigned saddr, const void* g) {
    asm volatile("cp.async.ca.shared.global [%0], [%1], 16;\n" :: "r"(saddr), "l"(g));
}
#define LDSM4(r0,r1,r2,r3,addr) \
    asm volatile("ldmatrix.sync.aligned.m8n8.x4.shared.b16 {%0,%1,%2,%3},[%4];" \
        : "=r"(r0),"=r"(r1),"=r"(r2),"=r"(r3) : "r"(addr))
#define LDSM4T(r0,r1,r2,r3,addr) \
    asm volatile("ldmatrix.sync.aligned.m8n8.x4.trans.shared.b16 {%0,%1,%2,%3},[%4];" \
        : "=r"(r0),"=r"(r1),"=r"(r2),"=r"(r3) : "r"(addr))

// ============================================================================
// fp32 -> packed fp16 plane
// ============================================================================
__global__ void __launch_bounds__(256) convf(const float* __restrict__ s,
        unsigned* __restrict__ d, int n4)
{
    int i = blockIdx.x * 256 + threadIdx.x;
    if (i >= n4) return;
    float4 x = ((const float4*)s)[i];
    uint2 H;
    H.x = pk16(x.x, x.y);
    H.y = pk16(x.z, x.w);
    ((uint2*)d)[i] = H;
}

// batched weight convert: 8 weights, z selects
struct WSrc { const float* p[8]; };
__global__ void __launch_bounds__(256) wconv_all(WSrc ws, unsigned* __restrict__ d)
{
    const float* __restrict__ W = ws.p[blockIdx.z];
    size_t base = (size_t)blockIdx.z * (WELTS / 2);
    int i = blockIdx.x * 256 + threadIdx.x + blockIdx.y * (256 * 96);
    float4 x = ((const float4*)W)[i];
    uint2 H;
    H.x = pk16(x.x, x.y);
    H.y = pk16(x.z, x.w);
    ((uint2*)(d + base))[i] = H;
}

// ============================================================================
// fp16 GEMM (R11-exact mainloop): C = A @ W + bias, single MMA term.
// BM=128, BN=128, BK=32, 3-stage cp.async, 256 threads = 8 warps (4m x 2n),
// warp tile 32x64, m16n8k16, ldmatrix fragments. 2 CTAs/SM.
// Template F16OUT: true -> packed fp16 output (QKV), false -> fp32 (out proj).
// ============================================================================
struct DualW {
    const unsigned* B_a; const float* bias_a; void* C_a;
    const unsigned* B_b; const float* bias_b; void* C_b;
};
struct GemmArgs {
    const unsigned* A;
    DualW w[3];
};

#define BM 128
#define BN 128
#define SA_T (BM * 20)            // 2560 u32/stage, A rows 80B (64 data + 16 pad)
#define SB_T (32 * 68)            // 2176 u32/stage, B rows 272B (256 data + 16 pad)
#define STG4 ((SA_T + SB_T) * 4)  // 18944 B
#define GEMM_SMEM (3 * STG4)      // 56832 B

template<bool F16OUT>
__global__ void __launch_bounds__(256, 2) gemm_f16(GemmArgs ga)
{
    extern __shared__ unsigned smg[];

    const DualW& w = ga.w[blockIdx.z];
    const int mBase = blockIdx.y * BM;
    const int nBase = blockIdx.x * BN;
    const bool low = (mBase < TXT_N);
    const unsigned* __restrict__ B = low ? w.B_a : w.B_b;
    const float* __restrict__ bias = low ? w.bias_a : w.bias_b;
    const size_t rowB = (size_t)DIMW * (F16OUT ? 2 : 4);
    char* __restrict__ C = (char*)(low ? w.C_a : w.C_b)
                           + (size_t)(low ? mBase : mBase - TXT_N) * rowB;
    const unsigned* __restrict__ A = ga.A;

    const int tid  = threadIdx.x;
    const int lane = tid & 31;
    const int warp = tid >> 5;
    const int wm = warp >> 1;     // 0..3
    const int wn = warp & 1;      // 0..1

    const unsigned smBase = (unsigned)__cvta_generic_to_shared(smg);
    const int quad = lane >> 3;
    const unsigned offA = (unsigned)((wm * 32 + (lane & 7) + (quad & 1) * 8) * 80 + (quad >> 1) * 16);
    const unsigned offB = (unsigned)(((lane & 7) + (quad & 1) * 8) * 272 + (wn * 64 + (quad >> 1) * 8) * 2);

    auto load_stage = [&](int kb, int buf) {
        unsigned base = smBase + buf * STG4;
        #pragma unroll
        for (int i = 0; i < 2; i++) {
            int c = tid + i * 256;               // 512 cpa for A (128 rows x 4 segs)
            int row = c >> 2, seg = c & 3;
            size_t g = (size_t)(mBase + row) * (DIMW / 2) + kb * 16 + seg * 4;
            cpa16(base + row * 80 + seg * 16, A + g);
        }
        #pragma unroll
        for (int i = 0; i < 2; i++) {
            int c = tid + i * 256;               // 512 cpa for B (32 rows x 16 segs)
            int row = c >> 4, seg = c & 15;
            size_t g = (size_t)(kb * 32 + row) * (DIMW / 2) + (nBase >> 1) + seg * 4;
            cpa16(base + SA_T * 4 + row * 272 + seg * 16, B + g);
        }
        asm volatile("cp.async.commit_group;\n");
    };

    float acc[2][8][4];
    #pragma unroll
    for (int i = 0; i < 2; i++)
        #pragma unroll
        for (int j = 0; j < 8; j++)
            #pragma unroll
            for (int p = 0; p < 4; p++) acc[i][j][p] = 0.f;

    const int NK = DIMW / 32;   // 96
    load_stage(0, 0);
    load_stage(1, 1);

    int buf = 0;
    for (int kb = 0; kb < NK; kb++) {
        if (kb + 2 < NK) {
            asm volatile("cp.async.wait_group 1;\n");
        } else {
            asm volatile("cp.async.wait_group 0;\n");
        }
        __syncthreads();
        if (kb + 2 < NK) load_stage(kb + 2, (kb + 2) % 3);

        const unsigned stb = smBase + buf * STG4;
        const unsigned aP = stb + offA;
        const unsigned bP = stb + SA_T * 4 + offB;

        #pragma unroll
        for (int k16 = 0; k16 < 2; k16++) {
            unsigned a[2][4];
            #pragma unroll
            for (int mt = 0; mt < 2; mt++)
                LDSM4(a[mt][0], a[mt][1], a[mt][2], a[mt][3], aP + mt * (16 * 80) + k16 * 32);
            #pragma unroll
            for (int p = 0; p < 4; p++) {
                unsigned bh[4];
                LDSM4T(bh[0], bh[1], bh[2], bh[3], bP + k16 * (16 * 272) + p * 32);
                #pragma unroll
                for (int h = 0; h < 2; h++)
                    #pragma unroll
                    for (int mt = 0; mt < 2; mt++)
                        mmaf(acc[mt][p * 2 + h], a[mt], bh[2 * h], bh[2 * h + 1]);
            }
        }
        buf = (buf + 1) % 3;
    }

    #pragma unroll
    for (int mt = 0; mt < 2; mt++) {
        int r = wm * 32 + mt * 16 + (lane >> 2);
        #pragma unroll
        for (int nt = 0; nt < 8; nt++) {
            int cg = nBase + wn * 64 + nt * 8 + (lane & 3) * 2;
            float b0 = bias[cg], b1 = bias[cg + 1];
            if (F16OUT) {
                unsigned* r0p = (unsigned*)(C + (size_t)r * rowB) + (cg >> 1);
                unsigned* r1p = (unsigned*)(C + (size_t)(r + 8) * rowB) + (cg >> 1);
                *r0p = pk16(acc[mt][nt][0] + b0, acc[mt][nt][1] + b1);
                *r1p = pk16(acc[mt][nt][2] + b0, acc[mt][nt][3] + b1);
            } else {
                float2 v0 = make_float2(acc[mt][nt][0] + b0, acc[mt][nt][1] + b1);
                float2 v1 = make_float2(acc[mt][nt][2] + b0, acc[mt][nt][3] + b1);
                *(float2*)((float*)(C + (size_t)r * rowB) + cg) = v0;
                *(float2*)((float*)(C + (size_t)(r + 8) * rowB) + cg) = v1;
            }
        }
    }
}

// ============================================================================
// Fused per-head RMSNorm + interleaved RoPE, in place on packed-fp16 q and k.
// fp32 math internally; 1 warp per (token, head).
// ============================================================================
__global__ void __launch_bounds__(128) norm_rope(unsigned* __restrict__ q,
        unsigned* __restrict__ k,
        const float* __restrict__ nq, const float* __restrict__ nk,
        const float* __restrict__ naq, const float* __restrict__ nak,
        const float* __restrict__ rc, const float* __restrict__ rs)
{
    const int gw   = blockIdx.x * 4 + (threadIdx.x >> 5);
    const int lane = threadIdx.x & 31;
    const int t = gw / NH, h = gw % NH;
    const size_t base = (size_t)t * (DIMW / 2) + h * (HD / 2) + lane * 2;
    const float* wq = (t < TXT_N) ? naq : nq;
    const float* wk = (t < TXT_N) ? nak : nk;
    const float4 c4 = *(const float4*)(rc + (size_t)t * HD + lane * 4);
    const float4 s4 = *(const float4*)(rs + (size_t)t * HD + lane * 4);
    const float4 w4q = *(const float4*)(wq + lane * 4);
    const float4 w4k = *(const float4*)(wk + lane * 4);

    #pragma unroll
    for (int which = 0; which < 2; which++) {
        unsigned* buf = which ? k : q;
        const float4 w4 = which ? w4k : w4q;
        uint2 xv = *(uint2*)(buf + base);
        float2 ab = up16(xv.x), cd = up16(xv.y);
        float x0 = ab.x, x1 = ab.y, x2 = cd.x, x3 = cd.y;
        float ss = x0 * x0 + x1 * x1 + x2 * x2 + x3 * x3;
        ss += __shfl_xor_sync(0xffffffffu, ss, 16);
        ss += __shfl_xor_sync(0xffffffffu, ss, 8);
        ss += __shfl_xor_sync(0xffffffffu, ss, 4);
        ss += __shfl_xor_sync(0xffffffffu, ss, 2);
        ss += __shfl_xor_sync(0xffffffffu, ss, 1);
        float r = rsqrtf(ss * (1.0f / HD) + 1e-6f);
        x0 *= r * w4.x; x1 *= r * w4.y; x2 *= r * w4.z; x3 *= r * w4.w;
        float y0 = x0 * c4.x - x1 * s4.x;
        float y1 = x1 * c4.y + x0 * s4.y;
        float y2 = x2 * c4.z - x3 * s4.z;
        float y3 = x3 * c4.w + x2 * s4.w;
        uint2 yv;
        yv.x = pk16(y0, y1);
        yv.y = pk16(y2, y3);
        *(uint2*)(buf + base) = yv;
    }
}

// ============================================================================
// Flash attention, all-fp16 MMA. q/k/v arrive packed fp16 -> zero-convert
// smem fills (uint4 copies). Epilogue writes packed fp16 plane.
// ============================================================================
#define QS 68
#define KS 68
#define VS 68
#define PS 36
#define V_OFF (64 * QS + 64 * KS)            // u32 offset of V
#define P_OFF (V_OFF + 64 * VS)
#define FLASH_SMEM ((P_OFF + 64 * PS) * 4)   // 61440 B

__global__ void __launch_bounds__(128) flash(const unsigned* __restrict__ q,
        const unsigned* __restrict__ k, const unsigned* __restrict__ v,
        unsigned* __restrict__ of)
{
    extern __shared__ unsigned sm[];
    unsigned* Qs = sm;
    unsigned* Ks = Qs + 64 * QS;
    unsigned* Vs = sm + V_OFF;
    unsigned* Ps = sm + P_OFF;
    const unsigned smBase = (unsigned)__cvta_generic_to_shared(sm);

    const int tid = threadIdx.x, lane = tid & 31, w = tid >> 5;
    const int qt = blockIdx.x, h = blockIdx.y;
    const int qb = qt * 64;
    const bool isref = (qb >= TXT_N) && (qb < TXT_N + REF_N);
    const int kv0 = isref ? TXT_N : 0;
    const int nkt = isref ? (REF_N / 64) : (STOT_N / 64);

    // ldmatrix.trans per-lane offset into V (k-rows x n-cols, 272B rows)
    const int quad = lane >> 3;
    const unsigned offV = (unsigned)(((lane & 7) + (quad & 1) * 8) * (VS * 4) + (quad >> 1) * 16);
    const unsigned vB = smBase + V_OFF * 4 + offV;

    // load Q tile 64x128 fp16 (64 u32/row): 8 iters x 128 thr x 16B
    #pragma unroll
    for (int i = 0; i < 8; i++) {
        int f = tid + i * 128;
        int row = f >> 4, g4 = f & 15;
        uint4 x = *(const uint4*)(q + (size_t)(qb + row) * (DIMW / 2) + h * (HD / 2) + g4 * 4);
        *(uint4*)&Qs[row * QS + g4 * 4] = x;
    }

    float O[16][4];
    #pragma unroll
    for (int i = 0; i < 16; i++)
        #pragma unroll
        for (int j = 0; j < 4; j++) O[i][j] = 0.f;
    float m0 = -1e30f, m1 = -1e30f, l0 = 0.f, l1 = 0.f;
    const int r0 = w * 16 + (lane >> 2);

    for (int it = 0; it < nkt; it++) {
        __syncthreads();
        const int kt0 = kv0 + it * 64;
        #pragma unroll
        for (int i = 0; i < 8; i++) {
            int f = tid + i * 128;
            int row = f >> 4, g4 = f & 15;
            size_t goff = (size_t)(kt0 + row) * (DIMW / 2) + h * (HD / 2) + g4 * 4;
            uint4 x = *(const uint4*)(k + goff);
            *(uint4*)&Ks[row * KS + g4 * 4] = x;
            uint4 y = *(const uint4*)(v + goff);
            *(uint4*)&Vs[row * VS + g4 * 4] = y;
        }
        __syncthreads();

        // S = Q @ K^T  (fp16 m16n8k16, 8 k-steps x 8 n-tiles)
        float s[8][4];
        #pragma unroll
        for (int i = 0; i < 8; i++)
            #pragma unroll
            for (int j = 0; j < 4; j++) s[i][j] = 0.f;
        #pragma unroll
        for (int ks = 0; ks < 8; ks++) {
            const int kp = ks * 8 + (lane & 3);
            unsigned a[4];
            a[0] = Qs[r0 * QS + kp];       a[1] = Qs[(r0 + 8) * QS + kp];
            a[2] = Qs[r0 * QS + kp + 4];   a[3] = Qs[(r0 + 8) * QS + kp + 4];
            #pragma unroll
            for (int nt = 0; nt < 8; nt++) {
                int bn = nt * 8 + (lane >> 2);
                mmaf(s[nt], a, Ks[bn * KS + kp], Ks[bn * KS + kp + 4]);
            }
        }
        // online softmax
        const float sc = 0.08838834764831845f;
        float rm0 = -1e30f, rm1 = -1e30f;
        #pragma unroll
        for (int nt = 0; nt < 8; nt++) {
            s[nt][0] *= sc; s[nt][1] *= sc; s[nt][2] *= sc; s[nt][3] *= sc;
            rm0 = fmaxf(rm0, fmaxf(s[nt][0], s[nt][1]));
            rm1 = fmaxf(rm1, fmaxf(s[nt][2], s[nt][3]));
        }
        rm0 = fmaxf(rm0, __shfl_xor_sync(0xffffffffu, rm0, 1));
        rm0 = fmaxf(rm0, __shfl_xor_sync(0xffffffffu, rm0, 2));
        rm1 = fmaxf(rm1, __shfl_xor_sync(0xffffffffu, rm1, 1));
        rm1 = fmaxf(rm1, __shfl_xor_sync(0xffffffffu, rm1, 2));
        float mn0 = fmaxf(m0, rm0), mn1 = fmaxf(m1, rm1);
        float al0 = __expf(m0 - mn0), al1 = __expf(m1 - mn1);
        float rs0 = 0.f, rs1 = 0.f;
        #pragma unroll
        for (int nt = 0; nt < 8; nt++) {
            s[nt][0] = __expf(s[nt][0] - mn0); s[nt][1] = __expf(s[nt][1] - mn0);
            s[nt][2] = __expf(s[nt][2] - mn1); s[nt][3] = __expf(s[nt][3] - mn1);
            rs0 += s[nt][0] + s[nt][1];
            rs1 += s[nt][2] + s[nt][3];
        }
        rs0 += __shfl_xor_sync(0xffffffffu, rs0, 1);
        rs0 += __shfl_xor_sync(0xffffffffu, rs0, 2);
        rs1 += __shfl_xor_sync(0xffffffffu, rs1, 1);
        rs1 += __shfl_xor_sync(0xffffffffu, rs1, 2);
        l0 = l0 * al0 + rs0; l1 = l1 * al1 + rs1;
        m0 = mn0; m1 = mn1;
        #pragma unroll
        for (int nt = 0; nt < 16; nt++) {
            O[nt][0] *= al0; O[nt][1] *= al0; O[nt][2] *= al1; O[nt][3] *= al1;
        }
        // P -> smem packed fp16
        #pragma unroll
        for (int nt = 0; nt < 8; nt++) {
            int pc = nt * 4 + (lane & 3);
            Ps[r0 * PS + pc]       = pk16(s[nt][0], s[nt][1]);
            Ps[(r0 + 8) * PS + pc] = pk16(s[nt][2], s[nt][3]);
        }
        __syncwarp();
        // O += P @ V  (fp16 m16n8k16, 4 k-steps x 8 n16-groups, ldmatrix.trans V)
        #pragma unroll
        for (int ks = 0; ks < 4; ks++) {
            const int kp = ks * 8 + (lane & 3);
            unsigned a[4];
            a[0] = Ps[r0 * PS + kp];       a[1] = Ps[(r0 + 8) * PS + kp];
            a[2] = Ps[r0 * PS + kp + 4];   a[3] = Ps[(r0 + 8) * PS + kp + 4];
            #pragma unroll
            for (int p = 0; p < 8; p++) {
                unsigned bh[4];
                LDSM4T(bh[0], bh[1], bh[2], bh[3], vB + ks * (16 * VS * 4) + p * 32);
                mmaf(O[p * 2],     a, bh[0], bh[1]);
                mmaf(O[p * 2 + 1], a, bh[2], bh[3]);
            }
        }
    }
    // epilogue: normalize + write packed fp16 plane
    const float i0 = 1.f / l0, i1 = 1.f / l1;
    const int tok0 = qb + r0;
    #pragma unroll
    for (int nt = 0; nt < 16; nt++) {
        int cp = h * (HD / 2) + nt * 4 + (lane & 3);
        of[(size_t)tok0 * (DIMW / 2) + cp]       = pk16(O[nt][0] * i0, O[nt][1] * i0);
        of[(size_t)(tok0 + 8) * (DIMW / 2) + cp] = pk16(O[nt][2] * i1, O[nt][3] * i1);
    }
}

extern "C" void kernel_launch(void* const* d_in, const int* in_sizes, int n_in,
                              void* d_out, int out_size) {
    const float* hs  = (const float*)d_in[0];
    const float* enc = (const float*)d_in[1];
    const float* rc  = (const float*)d_in[2];
    const float* rs  = (const float*)d_in[3];
    const float* wq  = (const float*)d_in[4];
    const float* bq  = (const float*)d_in[5];
    const float* wk  = (const float*)d_in[6];
    const float* bk  = (const float*)d_in[7];
    const float* wv  = (const float*)d_in[8];
    const float* bv  = (const float*)d_in[9];
    const float* waq = (const float*)d_in[10];
    const float* baq = (const float*)d_in[11];
    const float* wak = (const float*)d_in[12];
    const float* bak = (const float*)d_in[13];
    const float* wav = (const float*)d_in[14];
    const float* bav = (const float*)d_in[15];
    const float* nq  = (const float*)d_in[16];
    const float* nk  = (const float*)d_in[17];
    const float* naq = (const float*)d_in[18];
    const float* nak = (const float*)d_in[19];
    const float* wo  = (const float*)d_in[20];
    const float* bo  = (const float*)d_in[21];
    const float* wao = (const float*)d_in[22];
    const float* bao = (const float*)d_in[23];
    float* out = (float*)d_out;

    unsigned *qp, *kp, *vp, *afp, *wfp;
    cudaGetSymbolAddress((void**)&qp, g_q);
    cudaGetSymbolAddress((void**)&kp, g_k);
    cudaGetSymbolAddress((void**)&vp, g_v);
    cudaGetSymbolAddress((void**)&afp, g_af);
    cudaGetSymbolAddress((void**)&wfp, g_wf);

    cudaFuncSetAttribute(flash, cudaFuncAttributeMaxDynamicSharedMemorySize, FLASH_SMEM);
    cudaFuncSetAttribute(gemm_f16<true>, cudaFuncAttributeMaxDynamicSharedMemorySize, GEMM_SMEM);
    cudaFuncSetAttribute(gemm_f16<false>, cudaFuncAttributeMaxDynamicSharedMemorySize, GEMM_SMEM);

    const size_t WP = (size_t)WELTS / 2;
    const size_t AROW = DIMW / 2;

    // 0) weights (one batched launch; order wq wk wv waq wak wav wo wao)
    {
        WSrc ws;
        ws.p[0] = wq; ws.p[1] = wk; ws.p[2] = wv; ws.p[3] = waq;
        ws.p[4] = wak; ws.p[5] = wav; ws.p[6] = wo; ws.p[7] = wao;
        wconv_all<<<dim3(96, 96, 8), 256>>>(ws, wfp);
    }
    // 1-2) activations: rows [0,512)=enc, [512,2560)=hs
    convf<<<TXT_N * DIMW / 4 / 256, 256>>>(enc, afp, TXT_N * DIMW / 4);
    convf<<<SHID_N * DIMW / 4 / 256, 256>>>(hs, afp + TXT_N * AROW, SHID_N * DIMW / 4);

    // 3) fused QKV projection (fp16 output): grid (24, 20, 3), 2 CTAs/SM
    {
        GemmArgs ga;
        ga.A = afp;
        ga.w[0].B_a = wfp + 3ull * WP; ga.w[0].bias_a = baq; ga.w[0].C_a = qp;
        ga.w[0].B_b = wfp;            ga.w[0].bias_b = bq;
        ga.w[0].C_b = qp + TXT_N * AROW;
        ga.w[1].B_a = wfp + 4ull * WP; ga.w[1].bias_a = bak; ga.w[1].C_a = kp;
        ga.w[1].B_b = wfp + 1ull * WP; ga.w[1].bias_b = bk;
        ga.w[1].C_b = kp + TXT_N * AROW;
        ga.w[2].B_a = wfp + 5ull * WP; ga.w[2].bias_a = bav; ga.w[2].C_a = vp;
        ga.w[2].B_b = wfp + 2ull * WP; ga.w[2].bias_b = bv;
        ga.w[2].C_b = vp + TXT_N * AROW;
        gemm_f16<true><<<dim3(24, 20, 3), 256, GEMM_SMEM>>>(ga);
    }

    // 4) norm + rope (in place, packed fp16)
    norm_rope<<<STOT_N * NH / 4, 128>>>(qp, kp, nq, nk, naq, nak, rc, rs);

    // 5) flash (reads packed fp16 directly; writes packed fp16 plane)
    flash<<<dim3(STOT_N / 64, NH), 128, FLASH_SMEM>>>(qp, kp, vp, afp);

    // 6) fused out projection (fp32 output): grid (24, 20)
    {
        GemmArgs ga;
        ga.A = afp;
        ga.w[0].B_a = wfp + 7ull * WP; ga.w[0].bias_a = bao;
        ga.w[0].C_a = out + (size_t)SHID_N * DIMW;
        ga.w[0].B_b = wfp + 6ull * WP; ga.w[0].bias_b = bo;
        ga.w[0].C_b = out;
        ga.w[1] = ga.w[0]; ga.w[2] = ga.w[0];
        gemm_f16<false><<<dim3(24, 20, 1), 256, GEMM_SMEM>>>(ga);
    }
}

// round 14
// speedup vs baseline: 1.3708x; 1.0006x over previous
#include <cuda_runtime.h>
#include <cuda_fp16.h>
#include <math.h>

#define DIMW 3072
#define NH 24
#define HD 128
#define TXT_N 512
#define REF_N 512
#define STOT_N 2560
#define SHID_N 2048
#define WELTS (DIMW * DIMW)

// ---- scratch (device globals; no allocations allowed) ----
// q/k/v packed fp16 (2 per u32)
__device__ unsigned g_q[STOT_N * DIMW / 2];
__device__ unsigned g_k[STOT_N * DIMW / 2];
__device__ unsigned g_v[STOT_N * DIMW / 2];
// packed fp16 planes (2 fp16 per u32)
__device__ unsigned g_af[STOT_N * DIMW / 2];
__device__ unsigned g_wf[8ull * WELTS / 2];

// ---- helpers ----
__device__ __forceinline__ unsigned pk16(float a, float b) {   // a -> low half
    __half2 h = __floats2half2_rn(a, b);
    return *(unsigned*)&h;
}
__device__ __forceinline__ float2 up16(unsigned u) {
    return __half22float2(*(__half2*)&u);
}
__device__ __forceinline__ void mmaf(float* c, const unsigned* a, unsigned b0, unsigned b1) {
    asm volatile("mma.sync.aligned.m16n8k16.row.col.f32.f16.f16.f32 "
        "{%0,%1,%2,%3}, {%4,%5,%6,%7}, {%8,%9}, {%0,%1,%2,%3};\n"
        : "+f"(c[0]), "+f"(c[1]), "+f"(c[2]), "+f"(c[3])
        : "r"(a[0]), "r"(a[1]), "r"(a[2]), "r"(a[3]), "r"(b0), "r"(b1));
}
__device__ __forceinline__ void cpa16(unsigned saddr, const void* g) {
    asm volatile("cp.async.ca.shared.global [%0], [%1], 16;\n" :: "r"(saddr), "l"(g));
}
#define LDSM4(r0,r1,r2,r3,addr) \
    asm volatile("ldmatrix.sync.aligned.m8n8.x4.shared.b16 {%0,%1,%2,%3},[%4];" \
        : "=r"(r0),"=r"(r1),"=r"(r2),"=r"(r3) : "r"(addr))
#define LDSM4T(r0,r1,r2,r3,addr) \
    asm volatile("ldmatrix.sync.aligned.m8n8.x4.trans.shared.b16 {%0,%1,%2,%3},[%4];" \
        : "=r"(r0),"=r"(r1),"=r"(r2),"=r"(r3) : "r"(addr))

// ============================================================================
// fp32 -> packed fp16 plane (2 float4 per thread for MLP)
// ============================================================================
__global__ void __launch_bounds__(256) convf(const float* __restrict__ s,
        unsigned* __restrict__ d, int n4)
{
    int i = (blockIdx.x * 256 + threadIdx.x) * 2;
    if (i >= n4) return;
    float4 x = ((const float4*)s)[i];
    float4 y = ((const float4*)s)[i + 1];
    uint4 H;
    H.x = pk16(x.x, x.y);
    H.y = pk16(x.z, x.w);
    H.z = pk16(y.x, y.y);
    H.w = pk16(y.z, y.w);
    *(uint4*)(d + i * 2) = H;
}

// batched weight convert: 8 weights, z selects; 2 float4 per thread
struct WSrc { const float* p[8]; };
__global__ void __launch_bounds__(256) wconv_all(WSrc ws, unsigned* __restrict__ d)
{
    const float* __restrict__ W = ws.p[blockIdx.z];
    size_t base = (size_t)blockIdx.z * (WELTS / 2);
    int i = (blockIdx.x * 256 + threadIdx.x + blockIdx.y * (256 * 96)) * 2;
    float4 x = ((const float4*)W)[i];
    float4 y = ((const float4*)W)[i + 1];
    uint4 H;
    H.x = pk16(x.x, x.y);
    H.y = pk16(x.z, x.w);
    H.z = pk16(y.x, y.y);
    H.w = pk16(y.z, y.w);
    *(uint4*)(d + base + i * 2) = H;
}

// ============================================================================
// fp16 GEMM (R11-exact mainloop): C = A @ W + bias, single MMA term.
// BM=128, BN=128, BK=32, 3-stage cp.async, 256 threads = 8 warps (4m x 2n),
// warp tile 32x64, m16n8k16, ldmatrix fragments. 2 CTAs/SM.
// Template F16OUT: true -> packed fp16 output (QKV), false -> fp32 (out proj).
// ============================================================================
struct DualW {
    const unsigned* B_a; const float* bias_a; void* C_a;
    const unsigned* B_b; const float* bias_b; void* C_b;
};
struct GemmArgs {
    const unsigned* A;
    DualW w[3];
};

#define BM 128
#define BN 128
#define SA_T (BM * 20)            // 2560 u32/stage, A rows 80B (64 data + 16 pad)
#define SB_T (32 * 68)            // 2176 u32/stage, B rows 272B (256 data + 16 pad)
#define STG4 ((SA_T + SB_T) * 4)  // 18944 B
#define GEMM_SMEM (3 * STG4)      // 56832 B

template<bool F16OUT>
__global__ void __launch_bounds__(256, 2) gemm_f16(GemmArgs ga)
{
    extern __shared__ unsigned smg[];

    const DualW& w = ga.w[blockIdx.z];
    const int mBase = blockIdx.y * BM;
    const int nBase = blockIdx.x * BN;
    const bool low = (mBase < TXT_N);
    const unsigned* __restrict__ B = low ? w.B_a : w.B_b;
    const float* __restrict__ bias = low ? w.bias_a : w.bias_b;
    const size_t rowB = (size_t)DIMW * (F16OUT ? 2 : 4);
    char* __restrict__ C = (char*)(low ? w.C_a : w.C_b)
                           + (size_t)(low ? mBase : mBase - TXT_N) * rowB;
    const unsigned* __restrict__ A = ga.A;

    const int tid  = threadIdx.x;
    const int lane = tid & 31;
    const int warp = tid >> 5;
    const int wm = warp >> 1;     // 0..3
    const int wn = warp & 1;      // 0..1

    const unsigned smBase = (unsigned)__cvta_generic_to_shared(smg);
    const int quad = lane >> 3;
    const unsigned offA = (unsigned)((wm * 32 + (lane & 7) + (quad & 1) * 8) * 80 + (quad >> 1) * 16);
    const unsigned offB = (unsigned)(((lane & 7) + (quad & 1) * 8) * 272 + (wn * 64 + (quad >> 1) * 8) * 2);

    auto load_stage = [&](int kb, int buf) {
        unsigned base = smBase + buf * STG4;
        #pragma unroll
        for (int i = 0; i < 2; i++) {
            int c = tid + i * 256;               // 512 cpa for A (128 rows x 4 segs)
            int row = c >> 2, seg = c & 3;
            size_t g = (size_t)(mBase + row) * (DIMW / 2) + kb * 16 + seg * 4;
            cpa16(base + row * 80 + seg * 16, A + g);
        }
        #pragma unroll
        for (int i = 0; i < 2; i++) {
            int c = tid + i * 256;               // 512 cpa for B (32 rows x 16 segs)
            int row = c >> 4, seg = c & 15;
            size_t g = (size_t)(kb * 32 + row) * (DIMW / 2) + (nBase >> 1) + seg * 4;
            cpa16(base + SA_T * 4 + row * 272 + seg * 16, B + g);
        }
        asm volatile("cp.async.commit_group;\n");
    };

    float acc[2][8][4];
    #pragma unroll
    for (int i = 0; i < 2; i++)
        #pragma unroll
        for (int j = 0; j < 8; j++)
            #pragma unroll
            for (int p = 0; p < 4; p++) acc[i][j][p] = 0.f;

    const int NK = DIMW / 32;   // 96
    load_stage(0, 0);
    load_stage(1, 1);

    int buf = 0;
    for (int kb = 0; kb < NK; kb++) {
        if (kb + 2 < NK) {
            asm volatile("cp.async.wait_group 1;\n");
        } else {
            asm volatile("cp.async.wait_group 0;\n");
        }
        __syncthreads();
        if (kb + 2 < NK) load_stage(kb + 2, (kb + 2) % 3);

        const unsigned stb = smBase + buf * STG4;
        const unsigned aP = stb + offA;
        const unsigned bP = stb + SA_T * 4 + offB;

        #pragma unroll
        for (int k16 = 0; k16 < 2; k16++) {
            unsigned a[2][4];
            #pragma unroll
            for (int mt = 0; mt < 2; mt++)
                LDSM4(a[mt][0], a[mt][1], a[mt][2], a[mt][3], aP + mt * (16 * 80) + k16 * 32);
            #pragma unroll
            for (int p = 0; p < 4; p++) {
                unsigned bh[4];
                LDSM4T(bh[0], bh[1], bh[2], bh[3], bP + k16 * (16 * 272) + p * 32);
                #pragma unroll
                for (int h = 0; h < 2; h++)
                    #pragma unroll
                    for (int mt = 0; mt < 2; mt++)
                        mmaf(acc[mt][p * 2 + h], a[mt], bh[2 * h], bh[2 * h + 1]);
            }
        }
        buf = (buf + 1) % 3;
    }

    #pragma unroll
    for (int mt = 0; mt < 2; mt++) {
        int r = wm * 32 + mt * 16 + (lane >> 2);
        #pragma unroll
        for (int nt = 0; nt < 8; nt++) {
            int cg = nBase + wn * 64 + nt * 8 + (lane & 3) * 2;
            float b0 = bias[cg], b1 = bias[cg + 1];
            if (F16OUT) {
                unsigned* r0p = (unsigned*)(C + (size_t)r * rowB) + (cg >> 1);
                unsigned* r1p = (unsigned*)(C + (size_t)(r + 8) * rowB) + (cg >> 1);
                *r0p = pk16(acc[mt][nt][0] + b0, acc[mt][nt][1] + b1);
                *r1p = pk16(acc[mt][nt][2] + b0, acc[mt][nt][3] + b1);
            } else {
                float2 v0 = make_float2(acc[mt][nt][0] + b0, acc[mt][nt][1] + b1);
                float2 v1 = make_float2(acc[mt][nt][2] + b0, acc[mt][nt][3] + b1);
                *(float2*)((float*)(C + (size_t)r * rowB) + cg) = v0;
                *(float2*)((float*)(C + (size_t)(r + 8) * rowB) + cg) = v1;
            }
        }
    }
}

// ============================================================================
// Fused per-head RMSNorm + interleaved RoPE, in place on packed-fp16 q and k.
// ============================================================================
__global__ void __launch_bounds__(128) norm_rope(unsigned* __restrict__ q,
        unsigned* __restrict__ k,
        const float* __restrict__ nq, const float* __restrict__ nk,
        const float* __restrict__ naq, const float* __restrict__ nak,
        const float* __restrict__ rc, const float* __restrict__ rs)
{
    const int gw   = blockIdx.x * 4 + (threadIdx.x >> 5);
    const int lane = threadIdx.x & 31;
    const int t = gw / NH, h = gw % NH;
    const size_t base = (size_t)t * (DIMW / 2) + h * (HD / 2) + lane * 2;
    const float* wq = (t < TXT_N) ? naq : nq;
    const float* wk = (t < TXT_N) ? nak : nk;
    const float4 c4 = *(const float4*)(rc + (size_t)t * HD + lane * 4);
    const float4 s4 = *(const float4*)(rs + (size_t)t * HD + lane * 4);
    const float4 w4q = *(const float4*)(wq + lane * 4);
    const float4 w4k = *(const float4*)(wk + lane * 4);

    #pragma unroll
    for (int which = 0; which < 2; which++) {
        unsigned* buf = which ? k : q;
        const float4 w4 = which ? w4k : w4q;
        uint2 xv = *(uint2*)(buf + base);
        float2 ab = up16(xv.x), cd = up16(xv.y);
        float x0 = ab.x, x1 = ab.y, x2 = cd.x, x3 = cd.y;
        float ss = x0 * x0 + x1 * x1 + x2 * x2 + x3 * x3;
        ss += __shfl_xor_sync(0xffffffffu, ss, 16);
        ss += __shfl_xor_sync(0xffffffffu, ss, 8);
        ss += __shfl_xor_sync(0xffffffffu, ss, 4);
        ss += __shfl_xor_sync(0xffffffffu, ss, 2);
        ss += __shfl_xor_sync(0xffffffffu, ss, 1);
        float r = rsqrtf(ss * (1.0f / HD) + 1e-6f);
        x0 *= r * w4.x; x1 *= r * w4.y; x2 *= r * w4.z; x3 *= r * w4.w;
        float y0 = x0 * c4.x - x1 * s4.x;
        float y1 = x1 * c4.y + x0 * s4.y;
        float y2 = x2 * c4.z - x3 * s4.z;
        float y3 = x3 * c4.w + x2 * s4.w;
        uint2 yv;
        yv.x = pk16(y0, y1);
        yv.y = pk16(y2, y3);
        *(uint2*)(buf + base) = yv;
    }
}

// ============================================================================
// Flash attention, all-fp16 MMA, cp.async double-buffered K/V prefetch.
// K/V tile it+1 copy overlaps QK+softmax+PV of tile it. 96 KB smem, 2 CTAs/SM.
// ============================================================================
#define QS 68
#define KS 68
#define VS 68
#define PS 36
#define KTILE (64 * KS)
#define VTILE (64 * VS)
#define K_OFF (64 * QS)
#define V_OFF (K_OFF + 2 * KTILE)
#define P_OFF (V_OFF + 2 * VTILE)
#define FLASH_SMEM ((P_OFF + 64 * PS) * 4)   // 96256 B

__global__ void __launch_bounds__(128) flash(const unsigned* __restrict__ q,
        const unsigned* __restrict__ k, const unsigned* __restrict__ v,
        unsigned* __restrict__ of)
{
    extern __shared__ unsigned sm[];
    unsigned* Qs = sm;
    unsigned* Ps = sm + P_OFF;
    const unsigned smBase = (unsigned)__cvta_generic_to_shared(sm);

    const int tid = threadIdx.x, lane = tid & 31, w = tid >> 5;
    const int qt = blockIdx.x, h = blockIdx.y;
    const int qb = qt * 64;
    const bool isref = (qb >= TXT_N) && (qb < TXT_N + REF_N);
    const int kv0 = isref ? TXT_N : 0;
    const int nkt = isref ? (REF_N / 64) : (STOT_N / 64);

    // ldmatrix.trans per-lane offset into V (k-rows x n-cols, 272B rows)
    const int quad = lane >> 3;
    const unsigned offV = (unsigned)(((lane & 7) + (quad & 1) * 8) * (VS * 4) + (quad >> 1) * 16);

    // K/V tile prefetch via cp.async (one commit group per tile)
    auto load_kv = [&](int it, int b) {
        const int kt0 = kv0 + it * 64;
        const unsigned kBase = smBase + (K_OFF + b * KTILE) * 4;
        const unsigned vBase = smBase + (V_OFF + b * VTILE) * 4;
        #pragma unroll
        for (int i = 0; i < 8; i++) {
            int f = tid + i * 128;
            int row = f >> 4, g4 = f & 15;
            size_t goff = (size_t)(kt0 + row) * (DIMW / 2) + h * (HD / 2) + g4 * 4;
            cpa16(kBase + row * (KS * 4) + g4 * 16, k + goff);
            cpa16(vBase + row * (VS * 4) + g4 * 16, v + goff);
        }
        asm volatile("cp.async.commit_group;\n");
    };

    load_kv(0, 0);

    // load Q tile 64x128 fp16 (64 u32/row): 8 iters x 128 thr x 16B
    #pragma unroll
    for (int i = 0; i < 8; i++) {
        int f = tid + i * 128;
        int row = f >> 4, g4 = f & 15;
        uint4 x = *(const uint4*)(q + (size_t)(qb + row) * (DIMW / 2) + h * (HD / 2) + g4 * 4);
        *(uint4*)&Qs[row * QS + g4 * 4] = x;
    }

    float O[16][4];
    #pragma unroll
    for (int i = 0; i < 16; i++)
        #pragma unroll
        for (int j = 0; j < 4; j++) O[i][j] = 0.f;
    float m0 = -1e30f, m1 = -1e30f, l0 = 0.f, l1 = 0.f;
    const int r0 = w * 16 + (lane >> 2);

    for (int it = 0; it < nkt; it++) {
        const int bufc = it & 1;
        asm volatile("cp.async.wait_group 0;\n");
        __syncthreads();
        if (it + 1 < nkt) load_kv(it + 1, bufc ^ 1);

        const unsigned* Kb = sm + K_OFF + bufc * KTILE;
        const unsigned vB = smBase + (V_OFF + bufc * VTILE) * 4 + offV;

        // S = Q @ K^T  (fp16 m16n8k16, 8 k-steps x 8 n-tiles)
        float s[8][4];
        #pragma unroll
        for (int i = 0; i < 8; i++)
            #pragma unroll
            for (int j = 0; j < 4; j++) s[i][j] = 0.f;
        #pragma unroll
        for (int ks = 0; ks < 8; ks++) {
            const int kp = ks * 8 + (lane & 3);
            unsigned a[4];
            a[0] = Qs[r0 * QS + kp];       a[1] = Qs[(r0 + 8) * QS + kp];
            a[2] = Qs[r0 * QS + kp + 4];   a[3] = Qs[(r0 + 8) * QS + kp + 4];
            #pragma unroll
            for (int nt = 0; nt < 8; nt++) {
                int bn = nt * 8 + (lane >> 2);
                mmaf(s[nt], a, Kb[bn * KS + kp], Kb[bn * KS + kp + 4]);
            }
        }
        // online softmax
        const float sc = 0.08838834764831845f;
        float rm0 = -1e30f, rm1 = -1e30f;
        #pragma unroll
        for (int nt = 0; nt < 8; nt++) {
            s[nt][0] *= sc; s[nt][1] *= sc; s[nt][2] *= sc; s[nt][3] *= sc;
            rm0 = fmaxf(rm0, fmaxf(s[nt][0], s[nt][1]));
            rm1 = fmaxf(rm1, fmaxf(s[nt][2], s[nt][3]));
        }
        rm0 = fmaxf(rm0, __shfl_xor_sync(0xffffffffu, rm0, 1));
        rm0 = fmaxf(rm0, __shfl_xor_sync(0xffffffffu, rm0, 2));
        rm1 = fmaxf(rm1, __shfl_xor_sync(0xffffffffu, rm1, 1));
        rm1 = fmaxf(rm1, __shfl_xor_sync(0xffffffffu, rm1, 2));
        float mn0 = fmaxf(m0, rm0), mn1 = fmaxf(m1, rm1);
        float al0 = __expf(m0 - mn0), al1 = __expf(m1 - mn1);
        float rs0 = 0.f, rs1 = 0.f;
        #pragma unroll
        for (int nt = 0; nt < 8; nt++) {
            s[nt][0] = __expf(s[nt][0] - mn0); s[nt][1] = __expf(s[nt][1] - mn0);
            s[nt][2] = __expf(s[nt][2] - mn1); s[nt][3] = __expf(s[nt][3] - mn1);
            rs0 += s[nt][0] + s[nt][1];
            rs1 += s[nt][2] + s[nt][3];
        }
        rs0 += __shfl_xor_sync(0xffffffffu, rs0, 1);
        rs0 += __shfl_xor_sync(0xffffffffu, rs0, 2);
        rs1 += __shfl_xor_sync(0xffffffffu, rs1, 1);
        rs1 += __shfl_xor_sync(0xffffffffu, rs1, 2);
        l0 = l0 * al0 + rs0; l1 = l1 * al1 + rs1;
        m0 = mn0; m1 = mn1;
        #pragma unroll
        for (int nt = 0; nt < 16; nt++) {
            O[nt][0] *= al0; O[nt][1] *= al0; O[nt][2] *= al1; O[nt][3] *= al1;
        }
        // P -> smem packed fp16
        #pragma unroll
        for (int nt = 0; nt < 8; nt++) {
            int pc = nt * 4 + (lane & 3);
            Ps[r0 * PS + pc]       = pk16(s[nt][0], s[nt][1]);
            Ps[(r0 + 8) * PS + pc] = pk16(s[nt][2], s[nt][3]);
        }
        __syncwarp();
        // O += P @ V  (fp16 m16n8k16, 4 k-steps x 8 n16-groups, ldmatrix.trans V)
        #pragma unroll
        for (int ks = 0; ks < 4; ks++) {
            const int kp = ks * 8 + (lane & 3);
            unsigned a[4];
            a[0] = Ps[r0 * PS + kp];       a[1] = Ps[(r0 + 8) * PS + kp];
            a[2] = Ps[r0 * PS + kp + 4];   a[3] = Ps[(r0 + 8) * PS + kp + 4];
            #pragma unroll
            for (int p = 0; p < 8; p++) {
                unsigned bh[4];
                LDSM4T(bh[0], bh[1], bh[2], bh[3], vB + ks * (16 * VS * 4) + p * 32);
                mmaf(O[p * 2],     a, bh[0], bh[1]);
                mmaf(O[p * 2 + 1], a, bh[2], bh[3]);
            }
        }
    }
    // epilogue: normalize + write packed fp16 plane
    const float i0 = 1.f / l0, i1 = 1.f / l1;
    const int tok0 = qb + r0;
    #pragma unroll
    for (int nt = 0; nt < 16; nt++) {
        int cp = h * (HD / 2) + nt * 4 + (lane & 3);
        of[(size_t)tok0 * (DIMW / 2) + cp]       = pk16(O[nt][0] * i0, O[nt][1] * i0);
        of[(size_t)(tok0 + 8) * (DIMW / 2) + cp] = pk16(O[nt][2] * i1, O[nt][3] * i1);
    }
}

extern "C" void kernel_launch(void* const* d_in, const int* in_sizes, int n_in,
                              void* d_out, int out_size) {
    const float* hs  = (const float*)d_in[0];
    const float* enc = (const float*)d_in[1];
    const float* rc  = (const float*)d_in[2];
    const float* rs  = (const float*)d_in[3];
    const float* wq  = (const float*)d_in[4];
    const float* bq  = (const float*)d_in[5];
    const float* wk  = (const float*)d_in[6];
    const float* bk  = (const float*)d_in[7];
    const float* wv  = (const float*)d_in[8];
    const float* bv  = (const float*)d_in[9];
    const float* waq = (const float*)d_in[10];
    const float* baq = (const float*)d_in[11];
    const float* wak = (const float*)d_in[12];
    const float* bak = (const float*)d_in[13];
    const float* wav = (const float*)d_in[14];
    const float* bav = (const float*)d_in[15];
    const float* nq  = (const float*)d_in[16];
    const float* nk  = (const float*)d_in[17];
    const float* naq = (const float*)d_in[18];
    const float* nak = (const float*)d_in[19];
    const float* wo  = (const float*)d_in[20];
    const float* bo  = (const float*)d_in[21];
    const float* wao = (const float*)d_in[22];
    const float* bao = (const float*)d_in[23];
    float* out = (float*)d_out;

    unsigned *qp, *kp, *vp, *afp, *wfp;
    cudaGetSymbolAddress((void**)&qp, g_q);
    cudaGetSymbolAddress((void**)&kp, g_k);
    cudaGetSymbolAddress((void**)&vp, g_v);
    cudaGetSymbolAddress((void**)&afp, g_af);
    cudaGetSymbolAddress((void**)&wfp, g_wf);

    cudaFuncSetAttribute(flash, cudaFuncAttributeMaxDynamicSharedMemorySize, FLASH_SMEM);
    cudaFuncSetAttribute(gemm_f16<true>, cudaFuncAttributeMaxDynamicSharedMemorySize, GEMM_SMEM);
    cudaFuncSetAttribute(gemm_f16<false>, cudaFuncAttributeMaxDynamicSharedMemorySize, GEMM_SMEM);

    const size_t WP = (size_t)WELTS / 2;
    const size_t AROW = DIMW / 2;

    // 0) weights (one batched launch; 2 float4/thread)
    {
        WSrc ws;
        ws.p[0] = wq; ws.p[1] = wk; ws.p[2] = wv; ws.p[3] = waq;
        ws.p[4] = wak; ws.p[5] = wav; ws.p[6] = wo; ws.p[7] = wao;
        wconv_all<<<dim3(96, 48, 8), 256>>>(ws, wfp);
    }
    // 1-2) activations: rows [0,512)=enc, [512,2560)=hs
    convf<<<TXT_N * DIMW / 8 / 256, 256>>>(enc, afp, TXT_N * DIMW / 4);
    convf<<<SHID_N * DIMW / 8 / 256, 256>>>(hs, afp + TXT_N * AROW, SHID_N * DIMW / 4);

    // 3) fused QKV projection (fp16 output): grid (24, 20, 3), 2 CTAs/SM
    {
        GemmArgs ga;
        ga.A = afp;
        ga.w[0].B_a = wfp + 3ull * WP; ga.w[0].bias_a = baq; ga.w[0].C_a = qp;
        ga.w[0].B_b = wfp;            ga.w[0].bias_b = bq;
        ga.w[0].C_b = qp + TXT_N * AROW;
        ga.w[1].B_a = wfp + 4ull * WP; ga.w[1].bias_a = bak; ga.w[1].C_a = kp;
        ga.w[1].B_b = wfp + 1ull * WP; ga.w[1].bias_b = bk;
        ga.w[1].C_b = kp + TXT_N * AROW;
        ga.w[2].B_a = wfp + 5ull * WP; ga.w[2].bias_a = bav; ga.w[2].C_a = vp;
        ga.w[2].B_b = wfp + 2ull * WP; ga.w[2].bias_b = bv;
        ga.w[2].C_b = vp + TXT_N * AROW;
        gemm_f16<true><<<dim3(24, 20, 3), 256, GEMM_SMEM>>>(ga);
    }

    // 4) norm + rope (in place, packed fp16)
    norm_rope<<<STOT_N * NH / 4, 128>>>(qp, kp, nq, nk, naq, nak, rc, rs);

    // 5) flash (cp.async double-buffered K/V; writes packed fp16 plane)
    flash<<<dim3(STOT_N / 64, NH), 128, FLASH_SMEM>>>(qp, kp, vp, afp);

    // 6) fused out projection (fp32 output): grid (24, 20)
    {
        GemmArgs ga;
        ga.A = afp;
        ga.w[0].B_a = wfp + 7ull * WP; ga.w[0].bias_a = bao;
        ga.w[0].C_a = out + (size_t)SHID_N * DIMW;
        ga.w[0].B_b = wfp + 6ull * WP; ga.w[0].bias_b = bo;
        ga.w[0].C_b = out;
        ga.w[1] = ga.w[0]; ga.w[2] = ga.w[0];
        gemm_f16<false><<<dim3(24, 20, 1), 256, GEMM_SMEM>>>(ga);
    }
}

// round 15
// speedup vs baseline: 1.4507x; 1.0583x over previous
#include <cuda_runtime.h>
#include <cuda_fp16.h>
#include <math.h>

#define DIMW 3072
#define NH 24
#define HD 128
#define TXT_N 512
#define REF_N 512
#define STOT_N 2560
#define SHID_N 2048
#define WELTS (DIMW * DIMW)

// ---- scratch (device globals; no allocations allowed) ----
// q/k/v packed fp16 (2 per u32)
__device__ unsigned g_q[STOT_N * DIMW / 2];
__device__ unsigned g_k[STOT_N * DIMW / 2];
__device__ unsigned g_v[STOT_N * DIMW / 2];
// packed fp16 planes (2 fp16 per u32)
__device__ unsigned g_af[STOT_N * DIMW / 2];
__device__ unsigned g_wf[8ull * WELTS / 2];

// ---- helpers ----
__device__ __forceinline__ unsigned pk16(float a, float b) {   // a -> low half
    __half2 h = __floats2half2_rn(a, b);
    return *(unsigned*)&h;
}
__device__ __forceinline__ float2 up16(unsigned u) {
    return __half22float2(*(__half2*)&u);
}
__device__ __forceinline__ void mmaf(float* c, const unsigned* a, unsigned b0, unsigned b1) {
    asm volatile("mma.sync.aligned.m16n8k16.row.col.f32.f16.f16.f32 "
        "{%0,%1,%2,%3}, {%4,%5,%6,%7}, {%8,%9}, {%0,%1,%2,%3};\n"
        : "+f"(c[0]), "+f"(c[1]), "+f"(c[2]), "+f"(c[3])
        : "r"(a[0]), "r"(a[1]), "r"(a[2]), "r"(a[3]), "r"(b0), "r"(b1));
}
__device__ __forceinline__ void cpa16(unsigned saddr, const void* g) {
    asm volatile("cp.async.ca.shared.global [%0], [%1], 16;\n" :: "r"(saddr), "l"(g));
}
#define LDSM4(r0,r1,r2,r3,addr) \
    asm volatile("ldmatrix.sync.aligned.m8n8.x4.shared.b16 {%0,%1,%2,%3},[%4];" \
        : "=r"(r0),"=r"(r1),"=r"(r2),"=r"(r3) : "r"(addr))
#define LDSM4T(r0,r1,r2,r3,addr) \
    asm volatile("ldmatrix.sync.aligned.m8n8.x4.trans.shared.b16 {%0,%1,%2,%3},[%4];" \
        : "=r"(r0),"=r"(r1),"=r"(r2),"=r"(r3) : "r"(addr))

// ============================================================================
// fp32 -> packed fp16 plane (2 float4 per thread for MLP)
// ============================================================================
__global__ void __launch_bounds__(256) convf(const float* __restrict__ s,
        unsigned* __restrict__ d, int n4)
{
    int i = (blockIdx.x * 256 + threadIdx.x) * 2;
    if (i >= n4) return;
    float4 x = ((const float4*)s)[i];
    float4 y = ((const float4*)s)[i + 1];
    uint4 H;
    H.x = pk16(x.x, x.y);
    H.y = pk16(x.z, x.w);
    H.z = pk16(y.x, y.y);
    H.w = pk16(y.z, y.w);
    *(uint4*)(d + i * 2) = H;
}

// batched weight convert: 8 weights, z selects; 2 float4 per thread
struct WSrc { const float* p[8]; };
__global__ void __launch_bounds__(256) wconv_all(WSrc ws, unsigned* __restrict__ d)
{
    const float* __restrict__ W = ws.p[blockIdx.z];
    size_t base = (size_t)blockIdx.z * (WELTS / 2);
    int i = (blockIdx.x * 256 + threadIdx.x + blockIdx.y * (256 * 96)) * 2;
    float4 x = ((const float4*)W)[i];
    float4 y = ((const float4*)W)[i + 1];
    uint4 H;
    H.x = pk16(x.x, x.y);
    H.y = pk16(x.z, x.w);
    H.z = pk16(y.x, y.y);
    H.w = pk16(y.z, y.w);
    *(uint4*)(d + base + i * 2) = H;
}

// ============================================================================
// fp16 GEMM (R11-exact mainloop): C = A @ W + bias, single MMA term.
// BM=128, BN=128, BK=32, 3-stage cp.async, 256 threads = 8 warps (4m x 2n),
// warp tile 32x64, m16n8k16, ldmatrix fragments. 2 CTAs/SM.
// Template F16OUT: true -> packed fp16 output (QKV), false -> fp32 (out proj).
// ============================================================================
struct DualW {
    const unsigned* B_a; const float* bias_a; void* C_a;
    const unsigned* B_b; const float* bias_b; void* C_b;
};
struct GemmArgs {
    const unsigned* A;
    DualW w[3];
};

#define BM 128
#define BN 128
#define SA_T (BM * 20)            // 2560 u32/stage, A rows 80B (64 data + 16 pad)
#define SB_T (32 * 68)            // 2176 u32/stage, B rows 272B (256 data + 16 pad)
#define STG4 ((SA_T + SB_T) * 4)  // 18944 B
#define GEMM_SMEM (3 * STG4)      // 56832 B

template<bool F16OUT>
__global__ void __launch_bounds__(256, 2) gemm_f16(GemmArgs ga)
{
    extern __shared__ unsigned smg[];

    const DualW& w = ga.w[blockIdx.z];
    const int mBase = blockIdx.y * BM;
    const int nBase = blockIdx.x * BN;
    const bool low = (mBase < TXT_N);
    const unsigned* __restrict__ B = low ? w.B_a : w.B_b;
    const float* __restrict__ bias = low ? w.bias_a : w.bias_b;
    const size_t rowB = (size_t)DIMW * (F16OUT ? 2 : 4);
    char* __restrict__ C = (char*)(low ? w.C_a : w.C_b)
                           + (size_t)(low ? mBase : mBase - TXT_N) * rowB;
    const unsigned* __restrict__ A = ga.A;

    const int tid  = threadIdx.x;
    const int lane = tid & 31;
    const int warp = tid >> 5;
    const int wm = warp >> 1;     // 0..3
    const int wn = warp & 1;      // 0..1

    const unsigned smBase = (unsigned)__cvta_generic_to_shared(smg);
    const int quad = lane >> 3;
    const unsigned offA = (unsigned)((wm * 32 + (lane & 7) + (quad & 1) * 8) * 80 + (quad >> 1) * 16);
    const unsigned offB = (unsigned)(((lane & 7) + (quad & 1) * 8) * 272 + (wn * 64 + (quad >> 1) * 8) * 2);

    auto load_stage = [&](int kb, int buf) {
        unsigned base = smBase + buf * STG4;
        #pragma unroll
        for (int i = 0; i < 2; i++) {
            int c = tid + i * 256;               // 512 cpa for A (128 rows x 4 segs)
            int row = c >> 2, seg = c & 3;
            size_t g = (size_t)(mBase + row) * (DIMW / 2) + kb * 16 + seg * 4;
            cpa16(base + row * 80 + seg * 16, A + g);
        }
        #pragma unroll
        for (int i = 0; i < 2; i++) {
            int c = tid + i * 256;               // 512 cpa for B (32 rows x 16 segs)
            int row = c >> 4, seg = c & 15;
            size_t g = (size_t)(kb * 32 + row) * (DIMW / 2) + (nBase >> 1) + seg * 4;
            cpa16(base + SA_T * 4 + row * 272 + seg * 16, B + g);
        }
        asm volatile("cp.async.commit_group;\n");
    };

    float acc[2][8][4];
    #pragma unroll
    for (int i = 0; i < 2; i++)
        #pragma unroll
        for (int j = 0; j < 8; j++)
            #pragma unroll
            for (int p = 0; p < 4; p++) acc[i][j][p] = 0.f;

    const int NK = DIMW / 32;   // 96
    load_stage(0, 0);
    load_stage(1, 1);

    int buf = 0;
    for (int kb = 0; kb < NK; kb++) {
        if (kb + 2 < NK) {
            asm volatile("cp.async.wait_group 1;\n");
        } else {
            asm volatile("cp.async.wait_group 0;\n");
        }
        __syncthreads();
        if (kb + 2 < NK) load_stage(kb + 2, (kb + 2) % 3);

        const unsigned stb = smBase + buf * STG4;
        const unsigned aP = stb + offA;
        const unsigned bP = stb + SA_T * 4 + offB;

        #pragma unroll
        for (int k16 = 0; k16 < 2; k16++) {
            unsigned a[2][4];
            #pragma unroll
            for (int mt = 0; mt < 2; mt++)
                LDSM4(a[mt][0], a[mt][1], a[mt][2], a[mt][3], aP + mt * (16 * 80) + k16 * 32);
            #pragma unroll
            for (int p = 0; p < 4; p++) {
                unsigned bh[4];
                LDSM4T(bh[0], bh[1], bh[2], bh[3], bP + k16 * (16 * 272) + p * 32);
                #pragma unroll
                for (int h = 0; h < 2; h++)
                    #pragma unroll
                    for (int mt = 0; mt < 2; mt++)
                        mmaf(acc[mt][p * 2 + h], a[mt], bh[2 * h], bh[2 * h + 1]);
            }
        }
        buf = (buf + 1) % 3;
    }

    #pragma unroll
    for (int mt = 0; mt < 2; mt++) {
        int r = wm * 32 + mt * 16 + (lane >> 2);
        #pragma unroll
        for (int nt = 0; nt < 8; nt++) {
            int cg = nBase + wn * 64 + nt * 8 + (lane & 3) * 2;
            float b0 = bias[cg], b1 = bias[cg + 1];
            if (F16OUT) {
                unsigned* r0p = (unsigned*)(C + (size_t)r * rowB) + (cg >> 1);
                unsigned* r1p = (unsigned*)(C + (size_t)(r + 8) * rowB) + (cg >> 1);
                *r0p = pk16(acc[mt][nt][0] + b0, acc[mt][nt][1] + b1);
                *r1p = pk16(acc[mt][nt][2] + b0, acc[mt][nt][3] + b1);
            } else {
                float2 v0 = make_float2(acc[mt][nt][0] + b0, acc[mt][nt][1] + b1);
                float2 v1 = make_float2(acc[mt][nt][2] + b0, acc[mt][nt][3] + b1);
                *(float2*)((float*)(C + (size_t)r * rowB) + cg) = v0;
                *(float2*)((float*)(C + (size_t)(r + 8) * rowB) + cg) = v1;
            }
        }
    }
}

// ============================================================================
// Fused per-head RMSNorm + interleaved RoPE, in place on packed-fp16 q and k.
// ============================================================================
__global__ void __launch_bounds__(128) norm_rope(unsigned* __restrict__ q,
        unsigned* __restrict__ k,
        const float* __restrict__ nq, const float* __restrict__ nk,
        const float* __restrict__ naq, const float* __restrict__ nak,
        const float* __restrict__ rc, const float* __restrict__ rs)
{
    const int gw   = blockIdx.x * 4 + (threadIdx.x >> 5);
    const int lane = threadIdx.x & 31;
    const int t = gw / NH, h = gw % NH;
    const size_t base = (size_t)t * (DIMW / 2) + h * (HD / 2) + lane * 2;
    const float* wq = (t < TXT_N) ? naq : nq;
    const float* wk = (t < TXT_N) ? nak : nk;
    const float4 c4 = *(const float4*)(rc + (size_t)t * HD + lane * 4);
    const float4 s4 = *(const float4*)(rs + (size_t)t * HD + lane * 4);
    const float4 w4q = *(const float4*)(wq + lane * 4);
    const float4 w4k = *(const float4*)(wk + lane * 4);

    #pragma unroll
    for (int which = 0; which < 2; which++) {
        unsigned* buf = which ? k : q;
        const float4 w4 = which ? w4k : w4q;
        uint2 xv = *(uint2*)(buf + base);
        float2 ab = up16(xv.x), cd = up16(xv.y);
        float x0 = ab.x, x1 = ab.y, x2 = cd.x, x3 = cd.y;
        float ss = x0 * x0 + x1 * x1 + x2 * x2 + x3 * x3;
        ss += __shfl_xor_sync(0xffffffffu, ss, 16);
        ss += __shfl_xor_sync(0xffffffffu, ss, 8);
        ss += __shfl_xor_sync(0xffffffffu, ss, 4);
        ss += __shfl_xor_sync(0xffffffffu, ss, 2);
        ss += __shfl_xor_sync(0xffffffffu, ss, 1);
        float r = rsqrtf(ss * (1.0f / HD) + 1e-6f);
        x0 *= r * w4.x; x1 *= r * w4.y; x2 *= r * w4.z; x3 *= r * w4.w;
        float y0 = x0 * c4.x - x1 * s4.x;
        float y1 = x1 * c4.y + x0 * s4.y;
        float y2 = x2 * c4.z - x3 * s4.z;
        float y3 = x3 * c4.w + x2 * s4.w;
        uint2 yv;
        yv.x = pk16(y0, y1);
        yv.y = pk16(y2, y3);
        *(uint2*)(buf + base) = yv;
    }
}

// ============================================================================
// Flash attention, all-fp16 MMA, KV tile 128 (one softmax/sync block per
// 256 MMAs instead of per 128). Blocking uint4 loads (latency hidden by
// co-resident CTA, proven R14). smem 104.4 KB -> 2 CTAs/SM.
// ============================================================================
#define QS 68
#define KS 68
#define VS 68
#define PS 68
#define K_OFF (64 * QS)
#define V_OFF (K_OFF + 128 * KS)
#define P_OFF (V_OFF + 128 * VS)
#define FLASH_SMEM ((P_OFF + 64 * PS) * 4)   // 104448 B

__global__ void __launch_bounds__(128) flash(const unsigned* __restrict__ q,
        const unsigned* __restrict__ k, const unsigned* __restrict__ v,
        unsigned* __restrict__ of)
{
    extern __shared__ unsigned sm[];
    unsigned* Qs = sm;
    unsigned* Ks = sm + K_OFF;
    unsigned* Vs = sm + V_OFF;
    unsigned* Ps = sm + P_OFF;
    const unsigned smBase = (unsigned)__cvta_generic_to_shared(sm);

    const int tid = threadIdx.x, lane = tid & 31, w = tid >> 5;
    const int qt = blockIdx.x, h = blockIdx.y;
    const int qb = qt * 64;
    const bool isref = (qb >= TXT_N) && (qb < TXT_N + REF_N);
    const int kv0 = isref ? TXT_N : 0;
    const int nkt = isref ? (REF_N / 128) : (STOT_N / 128);

    // ldmatrix.trans per-lane offset into V (k-rows x n-cols)
    const int quad = lane >> 3;
    const unsigned offV = (unsigned)(((lane & 7) + (quad & 1) * 8) * (VS * 4) + (quad >> 1) * 16);
    const unsigned vB = smBase + V_OFF * 4 + offV;

    // load Q tile 64x128 fp16 (64 u32/row): 8 iters x 128 thr x 16B
    #pragma unroll
    for (int i = 0; i < 8; i++) {
        int f = tid + i * 128;
        int row = f >> 4, g4 = f & 15;
        uint4 x = *(const uint4*)(q + (size_t)(qb + row) * (DIMW / 2) + h * (HD / 2) + g4 * 4);
        *(uint4*)&Qs[row * QS + g4 * 4] = x;
    }

    float O[16][4];
    #pragma unroll
    for (int i = 0; i < 16; i++)
        #pragma unroll
        for (int j = 0; j < 4; j++) O[i][j] = 0.f;
    float m0 = -1e30f, m1 = -1e30f, l0 = 0.f, l1 = 0.f;
    const int r0 = w * 16 + (lane >> 2);

    for (int it = 0; it < nkt; it++) {
        __syncthreads();
        const int kt0 = kv0 + it * 128;
        // K/V tile 128x128 fp16: 16 iters x 128 thr x 16B each
        #pragma unroll
        for (int i = 0; i < 16; i++) {
            int f = tid + i * 128;
            int row = f >> 4, g4 = f & 15;
            size_t goff = (size_t)(kt0 + row) * (DIMW / 2) + h * (HD / 2) + g4 * 4;
            uint4 x = *(const uint4*)(k + goff);
            *(uint4*)&Ks[row * KS + g4 * 4] = x;
            uint4 y = *(const uint4*)(v + goff);
            *(uint4*)&Vs[row * VS + g4 * 4] = y;
        }
        __syncthreads();

        // S = Q @ K^T  (fp16 m16n8k16, 8 k-steps x 16 n-tiles)
        float s[16][4];
        #pragma unroll
        for (int i = 0; i < 16; i++)
            #pragma unroll
            for (int j = 0; j < 4; j++) s[i][j] = 0.f;
        #pragma unroll
        for (int ks = 0; ks < 8; ks++) {
            const int kp = ks * 8 + (lane & 3);
            unsigned a[4];
            a[0] = Qs[r0 * QS + kp];       a[1] = Qs[(r0 + 8) * QS + kp];
            a[2] = Qs[r0 * QS + kp + 4];   a[3] = Qs[(r0 + 8) * QS + kp + 4];
            #pragma unroll
            for (int nt = 0; nt < 16; nt++) {
                int bn = nt * 8 + (lane >> 2);
                mmaf(s[nt], a, Ks[bn * KS + kp], Ks[bn * KS + kp + 4]);
            }
        }
        // online softmax (one block per 128 kv)
        const float sc = 0.08838834764831845f;
        float rm0 = -1e30f, rm1 = -1e30f;
        #pragma unroll
        for (int nt = 0; nt < 16; nt++) {
            s[nt][0] *= sc; s[nt][1] *= sc; s[nt][2] *= sc; s[nt][3] *= sc;
            rm0 = fmaxf(rm0, fmaxf(s[nt][0], s[nt][1]));
            rm1 = fmaxf(rm1, fmaxf(s[nt][2], s[nt][3]));
        }
        rm0 = fmaxf(rm0, __shfl_xor_sync(0xffffffffu, rm0, 1));
        rm0 = fmaxf(rm0, __shfl_xor_sync(0xffffffffu, rm0, 2));
        rm1 = fmaxf(rm1, __shfl_xor_sync(0xffffffffu, rm1, 1));
        rm1 = fmaxf(rm1, __shfl_xor_sync(0xffffffffu, rm1, 2));
        float mn0 = fmaxf(m0, rm0), mn1 = fmaxf(m1, rm1);
        float al0 = __expf(m0 - mn0), al1 = __expf(m1 - mn1);
        float rs0 = 0.f, rs1 = 0.f;
        #pragma unroll
        for (int nt = 0; nt < 16; nt++) {
            s[nt][0] = __expf(s[nt][0] - mn0); s[nt][1] = __expf(s[nt][1] - mn0);
            s[nt][2] = __expf(s[nt][2] - mn1); s[nt][3] = __expf(s[nt][3] - mn1);
            rs0 += s[nt][0] + s[nt][1];
            rs1 += s[nt][2] + s[nt][3];
        }
        rs0 += __shfl_xor_sync(0xffffffffu, rs0, 1);
        rs0 += __shfl_xor_sync(0xffffffffu, rs0, 2);
        rs1 += __shfl_xor_sync(0xffffffffu, rs1, 1);
        rs1 += __shfl_xor_sync(0xffffffffu, rs1, 2);
        l0 = l0 * al0 + rs0; l1 = l1 * al1 + rs1;
        m0 = mn0; m1 = mn1;
        #pragma unroll
        for (int nt = 0; nt < 16; nt++) {
            O[nt][0] *= al0; O[nt][1] *= al0; O[nt][2] *= al1; O[nt][3] *= al1;
        }
        // P -> smem packed fp16 (64 rows x 64 u32)
        #pragma unroll
        for (int nt = 0; nt < 16; nt++) {
            int pc = nt * 4 + (lane & 3);
            Ps[r0 * PS + pc]       = pk16(s[nt][0], s[nt][1]);
            Ps[(r0 + 8) * PS + pc] = pk16(s[nt][2], s[nt][3]);
        }
        __syncwarp();
        // O += P @ V  (fp16 m16n8k16, 8 k-steps x 8 n16-groups, ldmatrix.trans V)
        #pragma unroll
        for (int ks = 0; ks < 8; ks++) {
            const int kp = ks * 8 + (lane & 3);
            unsigned a[4];
            a[0] = Ps[r0 * PS + kp];       a[1] = Ps[(r0 + 8) * PS + kp];
            a[2] = Ps[r0 * PS + kp + 4];   a[3] = Ps[(r0 + 8) * PS + kp + 4];
            #pragma unroll
            for (int p = 0; p < 8; p++) {
                unsigned bh[4];
                LDSM4T(bh[0], bh[1], bh[2], bh[3], vB + ks * (16 * VS * 4) + p * 32);
                mmaf(O[p * 2],     a, bh[0], bh[1]);
                mmaf(O[p * 2 + 1], a, bh[2], bh[3]);
            }
        }
    }
    // epilogue: normalize + write packed fp16 plane
    const float i0 = 1.f / l0, i1 = 1.f / l1;
    const int tok0 = qb + r0;
    #pragma unroll
    for (int nt = 0; nt < 16; nt++) {
        int cp = h * (HD / 2) + nt * 4 + (lane & 3);
        of[(size_t)tok0 * (DIMW / 2) + cp]       = pk16(O[nt][0] * i0, O[nt][1] * i0);
        of[(size_t)(tok0 + 8) * (DIMW / 2) + cp] = pk16(O[nt][2] * i1, O[nt][3] * i1);
    }
}

extern "C" void kernel_launch(void* const* d_in, const int* in_sizes, int n_in,
                              void* d_out, int out_size) {
    const float* hs  = (const float*)d_in[0];
    const float* enc = (const float*)d_in[1];
    const float* rc  = (const float*)d_in[2];
    const float* rs  = (const float*)d_in[3];
    const float* wq  = (const float*)d_in[4];
    const float* bq  = (const float*)d_in[5];
    const float* wk  = (const float*)d_in[6];
    const float* bk  = (const float*)d_in[7];
    const float* wv  = (const float*)d_in[8];
    const float* bv  = (const float*)d_in[9];
    const float* waq = (const float*)d_in[10];
    const float* baq = (const float*)d_in[11];
    const float* wak = (const float*)d_in[12];
    const float* bak = (const float*)d_in[13];
    const float* wav = (const float*)d_in[14];
    const float* bav = (const float*)d_in[15];
    const float* nq  = (const float*)d_in[16];
    const float* nk  = (const float*)d_in[17];
    const float* naq = (const float*)d_in[18];
    const float* nak = (const float*)d_in[19];
    const float* wo  = (const float*)d_in[20];
    const float* bo  = (const float*)d_in[21];
    const float* wao = (const float*)d_in[22];
    const float* bao = (const float*)d_in[23];
    float* out = (float*)d_out;

    unsigned *qp, *kp, *vp, *afp, *wfp;
    cudaGetSymbolAddress((void**)&qp, g_q);
    cudaGetSymbolAddress((void**)&kp, g_k);
    cudaGetSymbolAddress((void**)&vp, g_v);
    cudaGetSymbolAddress((void**)&afp, g_af);
    cudaGetSymbolAddress((void**)&wfp, g_wf);

    cudaFuncSetAttribute(flash, cudaFuncAttributeMaxDynamicSharedMemorySize, FLASH_SMEM);
    cudaFuncSetAttribute(gemm_f16<true>, cudaFuncAttributeMaxDynamicSharedMemorySize, GEMM_SMEM);
    cudaFuncSetAttribute(gemm_f16<false>, cudaFuncAttributeMaxDynamicSharedMemorySize, GEMM_SMEM);

    const size_t WP = (size_t)WELTS / 2;
    const size_t AROW = DIMW / 2;

    // 0) weights (one batched launch; 2 float4/thread)
    {
        WSrc ws;
        ws.p[0] = wq; ws.p[1] = wk; ws.p[2] = wv; ws.p[3] = waq;
        ws.p[4] = wak; ws.p[5] = wav; ws.p[6] = wo; ws.p[7] = wao;
        wconv_all<<<dim3(96, 48, 8), 256>>>(ws, wfp);
    }
    // 1-2) activations: rows [0,512)=enc, [512,2560)=hs
    convf<<<TXT_N * DIMW / 8 / 256, 256>>>(enc, afp, TXT_N * DIMW / 4);
    convf<<<SHID_N * DIMW / 8 / 256, 256>>>(hs, afp + TXT_N * AROW, SHID_N * DIMW / 4);

    // 3) fused QKV projection (fp16 output): grid (24, 20, 3), 2 CTAs/SM
    {
        GemmArgs ga;
        ga.A = afp;
        ga.w[0].B_a = wfp + 3ull * WP; ga.w[0].bias_a = baq; ga.w[0].C_a = qp;
        ga.w[0].B_b = wfp;            ga.w[0].bias_b = bq;
        ga.w[0].C_b = qp + TXT_N * AROW;
        ga.w[1].B_a = wfp + 4ull * WP; ga.w[1].bias_a = bak; ga.w[1].C_a = kp;
        ga.w[1].B_b = wfp + 1ull * WP; ga.w[1].bias_b = bk;
        ga.w[1].C_b = kp + TXT_N * AROW;
        ga.w[2].B_a = wfp + 5ull * WP; ga.w[2].bias_a = bav; ga.w[2].C_a = vp;
        ga.w[2].B_b = wfp + 2ull * WP; ga.w[2].bias_b = bv;
        ga.w[2].C_b = vp + TXT_N * AROW;
        gemm_f16<true><<<dim3(24, 20, 3), 256, GEMM_SMEM>>>(ga);
    }

    // 4) norm + rope (in place, packed fp16)
    norm_rope<<<STOT_N * NH / 4, 128>>>(qp, kp, nq, nk, naq, nak, rc, rs);

    // 5) flash (KV tile 128; writes packed fp16 plane)
    flash<<<dim3(STOT_N / 64, NH), 128, FLASH_SMEM>>>(qp, kp, vp, afp);

    // 6) fused out projection (fp32 output): grid (24, 20)
    {
        GemmArgs ga;
        ga.A = afp;
        ga.w[0].B_a = wfp + 7ull * WP; ga.w[0].bias_a = bao;
        ga.w[0].C_a = out + (size_t)SHID_N * DIMW;
        ga.w[0].B_b = wfp + 6ull * WP; ga.w[0].bias_b = bo;
        ga.w[0].C_b = out;
        ga.w[1] = ga.w[0]; ga.w[2] = ga.w[0];
        gemm_f16<false><<<dim3(24, 20, 1), 256, GEMM_SMEM>>>(ga);
    }
}